// round 12
// baseline (speedup 1.0000x reference)
#include <cuda_runtime.h>
#include <math.h>
#include <stdint.h>

// Problem dims
#define Bz   4
#define Nn   2048
#define Dd   256
#define HD   64
#define HID  512
#define Mrows (Bz*Nn)          // 8192
#define LZM  32                // Lanczos iterations
#define NCAP 80                // neighbor cap (max degree ~35 incl self)
#define CAP_E 45056            // smem CSR capacity (expected nnz ~34k)

// ---------------- device scratch (static; no allocations allowed) ----------
__device__ float g_scale2;     // 2 / lam_max

__device__ float g_xp[Mrows*Dd];
__device__ float g_x1[Mrows*Dd];
__device__ float g_q [Bz*4*Nn*HD];
__device__ float g_kk[Bz*4*Nn*HD];
__device__ float g_v [Bz*4*Nn*HD];
__device__ float g_o [Mrows*Dd];
__device__ float g_x2[Mrows*Dd];
__device__ float g_mt[Mrows*HID];
__device__ int   g_nbr[Nn*NCAP];
__device__ int   g_cnt[Nn];

// ---------------- cp.async helpers -----------------------------------------
__device__ __forceinline__ void cp16(float* dst, const float* src) {
    uint32_t d = (uint32_t)__cvta_generic_to_shared(dst);
    asm volatile("cp.async.cg.shared.global [%0], [%1], 16;\n" :: "r"(d), "l"(src));
}
__device__ __forceinline__ void cp_commit() { asm volatile("cp.async.commit_group;\n"); }
template<int N>
__device__ __forceinline__ void cp_wait() { asm volatile("cp.async.wait_group %0;\n" :: "n"(N)); }

// ---------------- packed f32x2 FMA (SASS FFMA2 — full fp32-core rate) -------
__device__ __forceinline__ void fma2(unsigned long long& d, unsigned long long a,
                                     unsigned long long b) {
    asm("fma.rn.f32x2 %0, %1, %2, %0;" : "+l"(d) : "l"(a), "l"(b));
}
__device__ __forceinline__ unsigned long long dup2(float v) {
    unsigned long long r;
    uint32_t u = __float_as_uint(v);
    asm("mov.b64 %0, {%1, %1};" : "=l"(r) : "r"(u));
    return r;
}
__device__ __forceinline__ void unpack2(unsigned long long p, float& lo, float& hi) {
    uint32_t l, h;
    asm("mov.b64 {%0, %1}, %2;" : "=r"(l), "=r"(h) : "l"(p));
    lo = __uint_as_float(l); hi = __uint_as_float(h);
}

// ===================== neighbor list build (ordered compaction) =============
__global__ void __launch_bounds__(256) k_build_nbr(const float* __restrict__ adj) {
    int n = blockIdx.x;
    int t = threadIdx.x;
    const float* row = adj + (size_t)n*Nn;
    int loc[8]; int c = 0;
    #pragma unroll
    for (int u=0; u<8; u++) {
        float a = row[t*8+u];
        if (a > 0.f) loc[c++] = t*8+u;
    }
    int lane = t & 31, w = t >> 5;
    int v = c;
    #pragma unroll
    for (int m=1; m<32; m<<=1) {
        int y = __shfl_up_sync(0xffffffffu, v, m);
        if (lane >= m) v += y;
    }
    __shared__ int wtot[8];
    if (lane == 31) wtot[w] = v;
    __syncthreads();
    int woff = 0;
    #pragma unroll
    for (int i=0; i<8; i++) woff += (i < w) ? wtot[i] : 0;
    int base2 = woff + v - c;   // exclusive prefix
    for (int i=0; i<c; i++) {
        int p = base2 + i;
        if (p < NCAP) g_nbr[n*NCAP + p] = loc[i];
    }
    if (t == 255) {
        int tot = woff + v;
        g_cnt[n] = (tot < NCAP) ? tot : NCAP;
    }
}

// ===================== fused sparse Lanczos (single block, smem CSR) =========
__device__ __forceinline__ float blk_reduce(float v, float* red, int t) {
    #pragma unroll
    for (int m=16; m>0; m>>=1) v += __shfl_xor_sync(0xffffffffu, v, m);
    if ((t & 31) == 0) red[t >> 5] = v;
    __syncthreads();
    if (t < 32) {
        float x = red[t];
        #pragma unroll
        for (int m=16; m>0; m>>=1) x += __shfl_xor_sync(0xffffffffu, x, m);
        if (t == 0) red[0] = x;
    }
    __syncthreads();
    float r = red[0];
    __syncthreads();
    return r;
}

__global__ void __launch_bounds__(1024) k_lz_fused(const float* __restrict__ L) {
    extern __shared__ float dyn[];
    float* vc  = dyn;                 // 2048
    float* vp  = vc + 2048;           // 2048
    float* red = vp + 2048;           // 128
    int*   snbr = (int*)(red + 128);  // CAP_E entries
    __shared__ float s_alpha[LZM], s_beta[LZM];
    __shared__ int iws[32];

    int t = threadIdx.x;
    int lane = t & 31, wid = t >> 5;
    int r0 = t, r1 = t + 1024;
    float deg0 = L[(size_t)r0*Nn + r0];
    float deg1 = L[(size_t)r1*Nn + r1];
    int cnt0 = g_cnt[r0], cnt1 = g_cnt[r1];
    int c0 = cnt0 - 1, c1 = cnt1 - 1;   // excluding self-loop
    const int* nb0 = g_nbr + r0*NCAP;
    const int* nb1 = g_nbr + r1*NCAP;

    // ---- exclusive scan of c0 over rows 0..1023 ----
    int incl = c0;
    #pragma unroll
    for (int m=1; m<32; m<<=1) { int y=__shfl_up_sync(0xffffffffu,incl,m); if (lane>=m) incl+=y; }
    if (lane == 31) iws[wid] = incl;
    __syncthreads();
    if (wid == 0) {
        int v = iws[lane];
        #pragma unroll
        for (int m=1; m<32; m<<=1) { int y=__shfl_up_sync(0xffffffffu,v,m); if (lane>=m) v+=y; }
        iws[lane] = v;
    }
    __syncthreads();
    int start0 = (wid>0 ? iws[wid-1] : 0) + incl - c0;
    int total0 = iws[31];
    __syncthreads();
    // ---- scan of c1 over rows 1024..2047, base total0 ----
    incl = c1;
    #pragma unroll
    for (int m=1; m<32; m<<=1) { int y=__shfl_up_sync(0xffffffffu,incl,m); if (lane>=m) incl+=y; }
    if (lane == 31) iws[wid] = incl;
    __syncthreads();
    if (wid == 0) {
        int v = iws[lane];
        #pragma unroll
        for (int m=1; m<32; m<<=1) { int y=__shfl_up_sync(0xffffffffu,v,m); if (lane>=m) v+=y; }
        iws[lane] = v;
    }
    __syncthreads();
    int start1 = total0 + (wid>0 ? iws[wid-1] : 0) + incl - c1;

    // ---- copy neighbor lists (minus self) into smem CSR ----
    bool fb0 = (start0 + c0 > CAP_E);
    bool fb1 = (start1 + c1 > CAP_E);
    if (!fb0) { int k=0; for (int i=0;i<cnt0;i++){ int jn=nb0[i]; if (jn!=r0) snbr[start0+k++]=jn; } }
    if (!fb1) { int k=0; for (int i=0;i<cnt1;i++){ int jn=nb1[i]; if (jn!=r1) snbr[start1+k++]=jn; } }

    // ---- init vector + normalize ----
    float a0 = sinf(0.7318f*(float)r0 + 0.2f) + 0.001f;
    float a1 = sinf(0.7318f*(float)r1 + 0.2f) + 0.001f;
    float nrm = blk_reduce(a0*a0 + a1*a1, red, t);
    float inv0 = rsqrtf(nrm);
    vc[r0] = a0*inv0; vc[r1] = a1*inv0;
    vp[r0] = 0.f;     vp[r1] = 0.f;
    float beta_prev = 0.f;
    __syncthreads();

    for (int j = 0; j < LZM; j++) {
        float s0 = 0.f, s1 = 0.f;
        if (!fb0) { for (int i=start0; i<start0+c0; i++) s0 += vc[snbr[i]]; }
        else      { for (int i=0; i<cnt0; i++){ int jn=nb0[i]; if (jn!=r0) s0 += vc[jn]; } }
        if (!fb1) { for (int i=start1; i<start1+c1; i++) s1 += vc[snbr[i]]; }
        else      { for (int i=0; i<cnt1; i++){ int jn=nb1[i]; if (jn!=r1) s1 += vc[jn]; } }
        float w0 = deg0*vc[r0] - s0 - beta_prev*vp[r0];
        float w1 = deg1*vc[r1] - s1 - beta_prev*vp[r1];
        // two-pass (cancellation-free): alpha, then explicit ||w - alpha*v||^2
        float alpha = blk_reduce(w0*vc[r0] + w1*vc[r1], red, t);
        w0 -= alpha*vc[r0]; w1 -= alpha*vc[r1];
        float tot = blk_reduce(w0*w0 + w1*w1, red, t);
        float beta_j = sqrtf(tot);
        float invb = rsqrtf(tot + 1e-30f);
        vp[r0] = vc[r0]; vp[r1] = vc[r1];
        vc[r0] = w0*invb; vc[r1] = w1*invb;
        if (t == 0) { s_alpha[j] = alpha; s_beta[j] = beta_j; }
        beta_prev = beta_j;
        __syncthreads();
    }

    // ---- warp-parallel fp32 multisection for lam_max, warp 0 ----
    if (t < 32) {
        float lo = s_alpha[0], hi = s_alpha[0];
        float sb2[LZM];
        for (int i=0;i<LZM;i++) {
            float r = (i>0?fabsf(s_beta[i-1]):0.f) + (i<LZM-1?fabsf(s_beta[i]):0.f);
            lo = fminf(lo, s_alpha[i]-r);
            hi = fmaxf(hi, s_alpha[i]+r);
            sb2[i] = (i>0) ? s_beta[i-1]*s_beta[i-1] : 0.f;
        }
        lo -= 1.f; hi += 1.f;
        for (int round=0; round<8; round++) {
            float w  = (hi-lo)*(1.0f/33.0f);
            float xp = lo + w*(float)(t+1);
            int cnt = 0;
            float d = s_alpha[0]-xp; if (d<0.f) cnt++;
            #pragma unroll 4
            for (int i=1;i<LZM;i++){
                if (d==0.f) d = -1e-30f;
                d = s_alpha[i]-xp - __fdividef(sb2[i], d);
                if (d<0.f) cnt++;
            }
            unsigned m = __ballot_sync(0xffffffffu, cnt >= LZM);
            if (m == 0u) {
                lo = lo + w*32.f;
            } else {
                int f = __ffs(m)-1;
                hi = lo + w*(float)(f+1);
                lo = lo + w*(float)f;
            }
        }
        if (t==0) {
            float lam = 0.5f*(lo+hi) + 1e-8f;
            g_scale2 = 2.0f/lam;
        }
    }
}
#define LZ_SMEM ((2048+2048+128)*4 + CAP_E*4)

// ===================== sparse xp: xp = (s2*deg-1)*x - s2*sum_nbr x ==========
__global__ void __launch_bounds__(256) k_xp_sparse(const float* __restrict__ L,
                                                   const float* __restrict__ x) {
    int row = blockIdx.x;          // 0..8191
    int b = row >> 11, n = row & 2047;
    int c = threadIdx.x;           // 0..255
    float deg = L[(size_t)n*Nn + n];
    float s2 = g_scale2;
    int cnt = g_cnt[n];
    const int* nb = g_nbr + n*NCAP;
    const float* xb = x + (size_t)b*Nn*Dd;
    float acc = 0.f;
    for (int i=0; i<cnt; i++) {
        int j = nb[i];
        if (j != n) acc += xb[(size_t)j*Dd + c];
    }
    float xv = xb[(size_t)n*Dd + c];
    g_xp[(size_t)row*Dd + c] = (s2*deg - 1.0f)*xv - s2*acc;
}

// ===================== sparse attention (exact) ==============================
__global__ void __launch_bounds__(256) k_attn_sp() {
    int wid = threadIdx.x >> 5, lane = threadIdx.x & 31;
    int gw = blockIdx.x*8 + wid;           // 0..16383
    int bh = gw >> 11;
    int n  = gw & 2047;
    int b = bh >> 2, h = bh & 3;

    const float* qg = g_q + ((size_t)bh*Nn + n)*HD;
    float2 q2 = *(const float2*)(qg + lane*2);

    int cnt = g_cnt[n];
    const int* nb = g_nbr + n*NCAP;

    int id[3] = {0,0,0};
    #pragma unroll
    for (int k=0;k<3;k++) { int j = lane + 32*k; if (j < cnt) id[k] = nb[j]; }

    const float* kg = g_kk + (size_t)bh*Nn*HD;
    float s[3] = {-1e30f,-1e30f,-1e30f};
    for (int j=0; j<cnt; j++) {
        int idx = __shfl_sync(0xffffffffu, id[j>>5], j&31);
        float2 k2 = *(const float2*)(kg + (size_t)idx*HD + lane*2);
        float d = q2.x*k2.x + q2.y*k2.y;
        #pragma unroll
        for (int m=16;m>0;m>>=1) d += __shfl_xor_sync(0xffffffffu, d, m);
        if (lane == (j&31) && (j>>5) == 0) s[0] = d*0.125f;
        if (lane == (j&31) && (j>>5) == 1) s[1] = d*0.125f;
        if (lane == (j&31) && (j>>5) == 2) s[2] = d*0.125f;
    }
    float mx = fmaxf(s[0], fmaxf(s[1], s[2]));
    #pragma unroll
    for (int m=16;m>0;m>>=1) mx = fmaxf(mx, __shfl_xor_sync(0xffffffffu, mx, m));
    float p[3];
    float l = 0.f;
    #pragma unroll
    for (int k=0;k<3;k++){ p[k] = __expf(s[k]-mx); l += p[k]; }
    #pragma unroll
    for (int m=16;m>0;m>>=1) l += __shfl_xor_sync(0xffffffffu, l, m);

    const float* vg = g_v + (size_t)bh*Nn*HD;
    float ox = 0.f, oy = 0.f;
    for (int j=0; j<cnt; j++) {
        float pj = __shfl_sync(0xffffffffu, p[j>>5], j&31);
        int  idx = __shfl_sync(0xffffffffu, id[j>>5], j&31);
        float2 v2 = *(const float2*)(vg + (size_t)idx*HD + lane*2);
        ox += pj*v2.x; oy += pj*v2.y;
    }
    float invl = 1.0f / l;
    float2 o2 = make_float2(ox*invl, oy*invl);
    *(float2*)(g_o + ((size_t)(b*Nn) + n)*Dd + h*HD + lane*2) = o2;
}

// ===== 32x256 GEMM (3-stage cp.async, 1 bar/stage, FFMA2, grid=256) =========
// 256 threads: tx=tid&31 (col lane), ty=tid>>5 (warp = 4 rows).
// Thread covers rows 4*ty..4*ty+3, cols {tx*4..+3} and {128+tx*4..+3}.
#define LDA_S 20
#define LDB_S 260
#define ASLOT (32*LDA_S)
#define BSLOT (16*LDB_S)

__device__ __forceinline__ void load_tiles32(const float* __restrict__ A, int lda,
                                             const float* __restrict__ B, int ldb,
                                             int k0, float* As, float* Bs, int tid) {
    if (tid < 128) { // A tile 32x16
        int r = tid >> 2, c = (tid & 3) * 4;
        cp16(As + r*LDA_S + c, A + (size_t)r*lda + k0 + c);
    }
    #pragma unroll
    for (int u=0; u<4; u++) { // B tile 16x256
        int o = tid*4 + u;                 // 0..1023
        int kk = o >> 6, c = (o & 63) * 4;
        cp16(Bs + kk*LDB_S + c, B + (size_t)(k0+kk)*ldb + c);
    }
}

__device__ __forceinline__ void mm32x256(const float* __restrict__ A, int lda,
                                         const float* __restrict__ B, int ldb,
                                         int K, float acc[4][8],
                                         float* As, float* Bs) {
    int tid = threadIdx.x;
    int tx = tid & 31, ty = tid >> 5;
    unsigned long long acc2[4][4];
    #pragma unroll
    for (int r=0;r<4;r++)
        #pragma unroll
        for (int p=0;p<4;p++) acc2[r][p] = 0ull;

    int T = K / 16;
    // 3-stage pipeline: prefetch stages 0,1 into slots 0,1
    load_tiles32(A, lda, B, ldb, 0,  As,         Bs,         tid);
    cp_commit();
    load_tiles32(A, lda, B, ldb, 16, As + ASLOT, Bs + BSLOT, tid);
    cp_commit();

    for (int t = 0; t < T; t++) {
        cp_wait<1>();          // stage t resident (t+1 may be in flight)
        __syncthreads();       // all warps done with stage t-1 -> slot (t+2)%3 free
        if (t+2 < T) {
            int slot = (t+2) % 3;
            load_tiles32(A, lda, B, ldb, (t+2)*16,
                         As + slot*ASLOT, Bs + slot*BSLOT, tid);
            cp_commit();
        } else {
            cp_commit();       // keep group count in sync for wait<1>
        }
        int cur = t % 3;
        const float* Asc = As + cur*ASLOT;
        const float* Bsc = Bs + cur*BSLOT;
        #pragma unroll
        for (int k4 = 0; k4 < 4; k4++) {
            float4 a[4];
            #pragma unroll
            for (int r=0;r<4;r++)
                a[r] = *(const float4*)(Asc + (4*ty+r)*LDA_S + k4*4);
            #pragma unroll
            for (int u=0;u<4;u++) {
                const float* brow = Bsc + (k4*4+u)*LDB_S;
                ulonglong2 b0 = *(const ulonglong2*)(brow + tx*4);
                ulonglong2 b1 = *(const ulonglong2*)(brow + 128 + tx*4);
                #pragma unroll
                for (int r=0;r<4;r++) {
                    float av = (u==0) ? a[r].x : (u==1) ? a[r].y : (u==2) ? a[r].z : a[r].w;
                    unsigned long long a2 = dup2(av);
                    fma2(acc2[r][0], a2, b0.x);
                    fma2(acc2[r][1], a2, b0.y);
                    fma2(acc2[r][2], a2, b1.x);
                    fma2(acc2[r][3], a2, b1.y);
                }
            }
        }
    }
    __syncthreads();
    #pragma unroll
    for (int r=0;r<4;r++)
        #pragma unroll
        for (int p=0;p<4;p++)
            unpack2(acc2[r][p], acc[r][2*p], acc[r][2*p+1]);
}

// row LayerNorm: row owned by one warp; lane holds cols tx*4..+3 and 128+tx*4..+3
__device__ __forceinline__ void ln_row_w(float v[8], const float* __restrict__ g,
                                         const float* __restrict__ be, int tx, bool do_relu) {
    float s = 0.f;
    #pragma unroll
    for (int u=0;u<8;u++) s += v[u];
    #pragma unroll
    for (int m=1;m<32;m<<=1) s += __shfl_xor_sync(0xffffffffu, s, m);
    float mu = s * (1.0f/256.0f);
    float q = 0.f;
    #pragma unroll
    for (int u=0;u<8;u++){ float d = v[u]-mu; q += d*d; }
    #pragma unroll
    for (int m=1;m<32;m<<=1) q += __shfl_xor_sync(0xffffffffu, q, m);
    float inv = rsqrtf(q*(1.0f/256.0f) + 1e-5f);
    #pragma unroll
    for (int u=0;u<8;u++){
        int col = (u<4) ? (tx*4+u) : (128 + tx*4 + (u-4));
        float t = (v[u]-mu)*inv*g[col] + be[col];
        if (do_relu) t = fmaxf(t, 0.f);
        v[u] = t;
    }
}

__device__ __forceinline__ void store_row8(float* dst, const float v[8], int tx) {
    *(float4*)(dst + tx*4)       = make_float4(v[0], v[1], v[2], v[3]);
    *(float4*)(dst + 128 + tx*4) = make_float4(v[4], v[5], v[6], v[7]);
}

#define GEMM_SMEM_DECL __shared__ float As[3*32*LDA_S]; __shared__ float Bs[3*16*LDB_S]

// ---- G2: x1 = relu(LN(xp@Wc + bc)) + x -------------------------------------
__global__ void __launch_bounds__(256, 2) k_gemm_x1(const float* __restrict__ x,
                                                 const float* __restrict__ Wc,
                                                 const float* __restrict__ bc,
                                                 const float* __restrict__ g1,
                                                 const float* __restrict__ be1) {
    GEMM_SMEM_DECL;
    float acc[4][8];
    const float* A = g_xp + (size_t)blockIdx.x*32*Dd;
    mm32x256(A, Dd, Wc, Dd, Dd, acc, As, Bs);
    int tx = threadIdx.x & 31, ty = threadIdx.x >> 5;
    #pragma unroll
    for (int rr=0; rr<4; rr++) {
        int row = blockIdx.x*32 + 4*ty + rr;
        float v[8];
        #pragma unroll
        for (int u=0;u<8;u++){
            int col = (u<4) ? (tx*4+u) : (128 + tx*4 + (u-4));
            v[u] = acc[rr][u] + bc[col];
        }
        ln_row_w(v, g1, be1, tx, true);
        const float* xr = x + (size_t)row*Dd;
        float4 xv0 = *(const float4*)(xr + tx*4);
        float4 xv1 = *(const float4*)(xr + 128 + tx*4);
        v[0]+=xv0.x; v[1]+=xv0.y; v[2]+=xv0.z; v[3]+=xv0.w;
        v[4]+=xv1.x; v[5]+=xv1.y; v[6]+=xv1.z; v[7]+=xv1.w;
        store_row8(g_x1 + (size_t)row*Dd, v, tx);
    }
}

// ---- G3: q/k/v = x1 @ W, stored (b,h,n,d) ----------------------------------
__global__ void __launch_bounds__(256, 2) k_gemm_qkv(const float* __restrict__ Wq,
                                                     const float* __restrict__ Wk,
                                                     const float* __restrict__ Wv) {
    GEMM_SMEM_DECL;
    float acc[4][8];
    const float* W = (blockIdx.y==0) ? Wq : (blockIdx.y==1) ? Wk : Wv;
    float* dst0 = (blockIdx.y==0) ? g_q : (blockIdx.y==1) ? g_kk : g_v;
    const float* A = g_x1 + (size_t)blockIdx.x*32*Dd;
    mm32x256(A, Dd, W, Dd, Dd, acc, As, Bs);
    int tx = threadIdx.x & 31, ty = threadIdx.x >> 5;
    int h0 = tx >> 4;            // head of col block 0 (cols tx*4 in [0,128))
    int co = (tx*4) & 63;        // offset within head
    #pragma unroll
    for (int rr=0; rr<4; rr++) {
        int row = blockIdx.x*32 + 4*ty + rr;
        int b = row >> 11, n = row & 2047;
        *(float4*)(dst0 + ((size_t)(b*4 + h0    )*Nn + n)*HD + co) =
            make_float4(acc[rr][0], acc[rr][1], acc[rr][2], acc[rr][3]);
        *(float4*)(dst0 + ((size_t)(b*4 + 2 + h0)*Nn + n)*HD + co) =
            make_float4(acc[rr][4], acc[rr][5], acc[rr][6], acc[rr][7]);
    }
}

// ---- G5: x2 = LN(x1 + o@Wo + bo) -------------------------------------------
__global__ void __launch_bounds__(256, 2) k_gemm_x2(const float* __restrict__ Wo,
                                                 const float* __restrict__ bo,
                                                 const float* __restrict__ g2,
                                                 const float* __restrict__ be2) {
    GEMM_SMEM_DECL;
    float acc[4][8];
    const float* A = g_o + (size_t)blockIdx.x*32*Dd;
    mm32x256(A, Dd, Wo, Dd, Dd, acc, As, Bs);
    int tx = threadIdx.x & 31, ty = threadIdx.x >> 5;
    #pragma unroll
    for (int rr=0; rr<4; rr++) {
        int row = blockIdx.x*32 + 4*ty + rr;
        const float* x1r = g_x1 + (size_t)row*Dd;
        float4 xv0 = *(const float4*)(x1r + tx*4);
        float4 xv1 = *(const float4*)(x1r + 128 + tx*4);
        int c0 = tx*4, c1 = 128 + tx*4;
        float v[8];
        v[0] = acc[rr][0] + bo[c0+0] + xv0.x;
        v[1] = acc[rr][1] + bo[c0+1] + xv0.y;
        v[2] = acc[rr][2] + bo[c0+2] + xv0.z;
        v[3] = acc[rr][3] + bo[c0+3] + xv0.w;
        v[4] = acc[rr][4] + bo[c1+0] + xv1.x;
        v[5] = acc[rr][5] + bo[c1+1] + xv1.y;
        v[6] = acc[rr][6] + bo[c1+2] + xv1.z;
        v[7] = acc[rr][7] + bo[c1+3] + xv1.w;
        ln_row_w(v, g2, be2, tx, false);
        store_row8(g_x2 + (size_t)row*Dd, v, tx);
    }
}

// ---- G6: mt = gelu(x2@W1 + b1)  (N=512 via 2 col blocks) -------------------
__global__ void __launch_bounds__(256, 2) k_gemm_m1(const float* __restrict__ W1,
                                                 const float* __restrict__ b1) {
    GEMM_SMEM_DECL;
    float acc[4][8];
    int cb = blockIdx.y; // 0 or 1
    const float* A = g_x2 + (size_t)blockIdx.x*32*Dd;
    mm32x256(A, Dd, W1 + cb*256, HID, Dd, acc, As, Bs);
    int tx = threadIdx.x & 31, ty = threadIdx.x >> 5;
    #pragma unroll
    for (int rr=0; rr<4; rr++) {
        int row = blockIdx.x*32 + 4*ty + rr;
        float v[8];
        #pragma unroll
        for (int u=0;u<8;u++){
            int col = (u<4) ? (tx*4+u) : (128 + tx*4 + (u-4));
            float t = acc[rr][u] + b1[cb*256 + col];
            v[u] = 0.5f*t*(1.0f + erff(t*0.70710678118654752f));
        }
        store_row8(g_mt + (size_t)row*HID + cb*256, v, tx);
    }
}

// ---- G7: out = LN(x2 + mt@W2 + b2) -----------------------------------------
__global__ void __launch_bounds__(256, 2) k_gemm_out(const float* __restrict__ W2,
                                                  const float* __restrict__ b2,
                                                  const float* __restrict__ g3,
                                                  const float* __restrict__ be3,
                                                  float* __restrict__ out) {
    GEMM_SMEM_DECL;
    float acc[4][8];
    const float* A = g_mt + (size_t)blockIdx.x*32*HID;
    mm32x256(A, HID, W2, Dd, HID, acc, As, Bs);
    int tx = threadIdx.x & 31, ty = threadIdx.x >> 5;
    #pragma unroll
    for (int rr=0; rr<4; rr++) {
        int row = blockIdx.x*32 + 4*ty + rr;
        const float* x2r = g_x2 + (size_t)row*Dd;
        float4 xv0 = *(const float4*)(x2r + tx*4);
        float4 xv1 = *(const float4*)(x2r + 128 + tx*4);
        int c0 = tx*4, c1 = 128 + tx*4;
        float v[8];
        v[0] = acc[rr][0] + b2[c0+0] + xv0.x;
        v[1] = acc[rr][1] + b2[c0+1] + xv0.y;
        v[2] = acc[rr][2] + b2[c0+2] + xv0.z;
        v[3] = acc[rr][3] + b2[c0+3] + xv0.w;
        v[4] = acc[rr][4] + b2[c1+0] + xv1.x;
        v[5] = acc[rr][5] + b2[c1+1] + xv1.y;
        v[6] = acc[rr][6] + b2[c1+2] + xv1.z;
        v[7] = acc[rr][7] + b2[c1+3] + xv1.w;
        ln_row_w(v, g3, be3, tx, false);
        store_row8(out + (size_t)row*Dd, v, tx);
    }
}

// ============================ launch =========================================
extern "C" void kernel_launch(void* const* d_in, const int* in_sizes, int n_in,
                              void* d_out, int out_size) {
    const float* x   = (const float*)d_in[0];
    const float* L   = (const float*)d_in[1];
    const float* adj = (const float*)d_in[2];
    const float* Wc  = (const float*)d_in[3];
    const float* bc  = (const float*)d_in[4];
    const float* g1  = (const float*)d_in[5];
    const float* be1 = (const float*)d_in[6];
    const float* Wq  = (const float*)d_in[7];
    const float* Wk  = (const float*)d_in[8];
    const float* Wv  = (const float*)d_in[9];
    const float* Wo  = (const float*)d_in[10];
    const float* bo  = (const float*)d_in[11];
    const float* g2  = (const float*)d_in[12];
    const float* be2 = (const float*)d_in[13];
    const float* W1  = (const float*)d_in[14];
    const float* b1  = (const float*)d_in[15];
    const float* W2  = (const float*)d_in[16];
    const float* b2  = (const float*)d_in[17];
    const float* g3  = (const float*)d_in[18];
    const float* be3 = (const float*)d_in[19];
    float* out = (float*)d_out;

    cudaFuncSetAttribute(k_lz_fused, cudaFuncAttributeMaxDynamicSharedMemorySize, LZ_SMEM);

    k_build_nbr<<<Nn, 256>>>(adj);                      // 1
    k_lz_fused <<<1, 1024, LZ_SMEM>>>(L);               // 2
    k_xp_sparse<<<Mrows, 256>>>(L, x);                  // 3
    k_gemm_x1  <<<Mrows/32, 256>>>(x, Wc, bc, g1, be1); // 4
    k_gemm_qkv <<<dim3(Mrows/32, 3), 256>>>(Wq, Wk, Wv);// 5
    k_attn_sp  <<<Bz*4*Nn/8, 256>>>();                  // 6
    k_gemm_x2  <<<Mrows/32, 256>>>(Wo, bo, g2, be2);    // 7
    k_gemm_m1  <<<dim3(Mrows/32, 2), 256>>>(W1, b1);    // 8
    k_gemm_out <<<Mrows/32, 256>>>(W2, b2, g3, be3, out); // 9
}

// round 13
// speedup vs baseline: 1.0614x; 1.0614x over previous
#include <cuda_runtime.h>
#include <math.h>
#include <stdint.h>

// Problem dims
#define Bz   4
#define Nn   2048
#define Dd   256
#define HD   64
#define HID  512
#define Mrows (Bz*Nn)          // 8192
#define LZM  32                // Lanczos iterations
#define NCAP 80                // neighbor cap (max degree ~35 incl self)
#define CAP_E 45056            // smem CSR capacity (expected nnz ~34k)

// ---------------- device scratch (static; no allocations allowed) ----------
__device__ float g_scale2;     // 2 / lam_max

__device__ float g_xp[Mrows*Dd];
__device__ float g_x1[Mrows*Dd];
__device__ float g_q [Bz*4*Nn*HD];
__device__ float g_kk[Bz*4*Nn*HD];
__device__ float g_v [Bz*4*Nn*HD];
__device__ float g_o [Mrows*Dd];
__device__ float g_x2[Mrows*Dd];
__device__ float g_mt[Mrows*HID];
__device__ int   g_nbr[Nn*NCAP];
__device__ int   g_cnt[Nn];

// ---------------- cp.async helpers -----------------------------------------
__device__ __forceinline__ void cp16(float* dst, const float* src) {
    uint32_t d = (uint32_t)__cvta_generic_to_shared(dst);
    asm volatile("cp.async.cg.shared.global [%0], [%1], 16;\n" :: "r"(d), "l"(src));
}
__device__ __forceinline__ void cp_commit() { asm volatile("cp.async.commit_group;\n"); }
template<int N>
__device__ __forceinline__ void cp_wait() { asm volatile("cp.async.wait_group %0;\n" :: "n"(N)); }

// ---------------- packed f32x2 FMA (SASS FFMA2 — full fp32-core rate) -------
__device__ __forceinline__ void fma2(unsigned long long& d, unsigned long long a,
                                     unsigned long long b) {
    asm("fma.rn.f32x2 %0, %1, %2, %0;" : "+l"(d) : "l"(a), "l"(b));
}
__device__ __forceinline__ unsigned long long dup2(float v) {
    unsigned long long r;
    uint32_t u = __float_as_uint(v);
    asm("mov.b64 %0, {%1, %1};" : "=l"(r) : "r"(u));
    return r;
}
__device__ __forceinline__ void unpack2(unsigned long long p, float& lo, float& hi) {
    uint32_t l, h;
    asm("mov.b64 {%0, %1}, %2;" : "=r"(l), "=r"(h) : "l"(p));
    lo = __uint_as_float(l); hi = __uint_as_float(h);
}

// ===================== neighbor list build (ordered compaction) =============
__global__ void __launch_bounds__(256) k_build_nbr(const float* __restrict__ adj, int base) {
    int n = base + blockIdx.x;
    int t = threadIdx.x;
    const float* row = adj + (size_t)n*Nn;
    int loc[8]; int c = 0;
    #pragma unroll
    for (int u=0; u<8; u++) {
        float a = row[t*8+u];
        if (a > 0.f) loc[c++] = t*8+u;
    }
    int lane = t & 31, w = t >> 5;
    int v = c;
    #pragma unroll
    for (int m=1; m<32; m<<=1) {
        int y = __shfl_up_sync(0xffffffffu, v, m);
        if (lane >= m) v += y;
    }
    __shared__ int wtot[8];
    if (lane == 31) wtot[w] = v;
    __syncthreads();
    int woff = 0;
    #pragma unroll
    for (int i=0; i<8; i++) woff += (i < w) ? wtot[i] : 0;
    int base2 = woff + v - c;   // exclusive prefix
    for (int i=0; i<c; i++) {
        int p = base2 + i;
        if (p < NCAP) g_nbr[n*NCAP + p] = loc[i];
    }
    if (t == 255) {
        int tot = woff + v;
        g_cnt[n] = (tot < NCAP) ? tot : NCAP;
    }
}

// ===================== fused sparse Lanczos (single block, smem CSR) =========
__device__ __forceinline__ float blk_reduce(float v, float* red, int t) {
    #pragma unroll
    for (int m=16; m>0; m>>=1) v += __shfl_xor_sync(0xffffffffu, v, m);
    if ((t & 31) == 0) red[t >> 5] = v;
    __syncthreads();
    if (t < 32) {
        float x = red[t];
        #pragma unroll
        for (int m=16; m>0; m>>=1) x += __shfl_xor_sync(0xffffffffu, x, m);
        if (t == 0) red[0] = x;
    }
    __syncthreads();
    float r = red[0];
    __syncthreads();
    return r;
}

__global__ void __launch_bounds__(1024) k_lz_fused(const float* __restrict__ L) {
    extern __shared__ float dyn[];
    float* vc  = dyn;                 // 2048
    float* vp  = vc + 2048;           // 2048
    float* red = vp + 2048;           // 128
    int*   snbr = (int*)(red + 128);  // CAP_E entries
    __shared__ float s_alpha[LZM], s_beta[LZM];
    __shared__ int iws[32];

    int t = threadIdx.x;
    int lane = t & 31, wid = t >> 5;
    int r0 = t, r1 = t + 1024;
    float deg0 = L[(size_t)r0*Nn + r0];
    float deg1 = L[(size_t)r1*Nn + r1];
    int cnt0 = g_cnt[r0], cnt1 = g_cnt[r1];
    int c0 = cnt0 - 1, c1 = cnt1 - 1;   // excluding self-loop
    const int* nb0 = g_nbr + r0*NCAP;
    const int* nb1 = g_nbr + r1*NCAP;

    // ---- exclusive scan of c0 over rows 0..1023 ----
    int incl = c0;
    #pragma unroll
    for (int m=1; m<32; m<<=1) { int y=__shfl_up_sync(0xffffffffu,incl,m); if (lane>=m) incl+=y; }
    if (lane == 31) iws[wid] = incl;
    __syncthreads();
    if (wid == 0) {
        int v = iws[lane];
        #pragma unroll
        for (int m=1; m<32; m<<=1) { int y=__shfl_up_sync(0xffffffffu,v,m); if (lane>=m) v+=y; }
        iws[lane] = v;
    }
    __syncthreads();
    int start0 = (wid>0 ? iws[wid-1] : 0) + incl - c0;
    int total0 = iws[31];
    __syncthreads();
    // ---- scan of c1 over rows 1024..2047, base total0 ----
    incl = c1;
    #pragma unroll
    for (int m=1; m<32; m<<=1) { int y=__shfl_up_sync(0xffffffffu,incl,m); if (lane>=m) incl+=y; }
    if (lane == 31) iws[wid] = incl;
    __syncthreads();
    if (wid == 0) {
        int v = iws[lane];
        #pragma unroll
        for (int m=1; m<32; m<<=1) { int y=__shfl_up_sync(0xffffffffu,v,m); if (lane>=m) v+=y; }
        iws[lane] = v;
    }
    __syncthreads();
    int start1 = total0 + (wid>0 ? iws[wid-1] : 0) + incl - c1;

    // ---- copy neighbor lists (minus self) into smem CSR ----
    bool fb0 = (start0 + c0 > CAP_E);
    bool fb1 = (start1 + c1 > CAP_E);
    if (!fb0) { int k=0; for (int i=0;i<cnt0;i++){ int jn=nb0[i]; if (jn!=r0) snbr[start0+k++]=jn; } }
    if (!fb1) { int k=0; for (int i=0;i<cnt1;i++){ int jn=nb1[i]; if (jn!=r1) snbr[start1+k++]=jn; } }

    // ---- init vector + normalize ----
    float a0 = sinf(0.7318f*(float)r0 + 0.2f) + 0.001f;
    float a1 = sinf(0.7318f*(float)r1 + 0.2f) + 0.001f;
    float nrm = blk_reduce(a0*a0 + a1*a1, red, t);
    float inv0 = rsqrtf(nrm);
    vc[r0] = a0*inv0; vc[r1] = a1*inv0;
    vp[r0] = 0.f;     vp[r1] = 0.f;
    float beta_prev = 0.f;
    __syncthreads();

    for (int j = 0; j < LZM; j++) {
        float s0 = 0.f, s1 = 0.f;
        if (!fb0) { for (int i=start0; i<start0+c0; i++) s0 += vc[snbr[i]]; }
        else      { for (int i=0; i<cnt0; i++){ int jn=nb0[i]; if (jn!=r0) s0 += vc[jn]; } }
        if (!fb1) { for (int i=start1; i<start1+c1; i++) s1 += vc[snbr[i]]; }
        else      { for (int i=0; i<cnt1; i++){ int jn=nb1[i]; if (jn!=r1) s1 += vc[jn]; } }
        float w0 = deg0*vc[r0] - s0 - beta_prev*vp[r0];
        float w1 = deg1*vc[r1] - s1 - beta_prev*vp[r1];
        // two-pass (cancellation-free): alpha, then explicit ||w - alpha*v||^2
        float alpha = blk_reduce(w0*vc[r0] + w1*vc[r1], red, t);
        w0 -= alpha*vc[r0]; w1 -= alpha*vc[r1];
        float tot = blk_reduce(w0*w0 + w1*w1, red, t);
        float beta_j = sqrtf(tot);
        float invb = rsqrtf(tot + 1e-30f);
        vp[r0] = vc[r0]; vp[r1] = vc[r1];
        vc[r0] = w0*invb; vc[r1] = w1*invb;
        if (t == 0) { s_alpha[j] = alpha; s_beta[j] = beta_j; }
        beta_prev = beta_j;
        __syncthreads();
    }

    // ---- warp-parallel fp32 multisection for lam_max, warp 0 ----
    if (t < 32) {
        float lo = s_alpha[0], hi = s_alpha[0];
        float sb2[LZM];
        for (int i=0;i<LZM;i++) {
            float r = (i>0?fabsf(s_beta[i-1]):0.f) + (i<LZM-1?fabsf(s_beta[i]):0.f);
            lo = fminf(lo, s_alpha[i]-r);
            hi = fmaxf(hi, s_alpha[i]+r);
            sb2[i] = (i>0) ? s_beta[i-1]*s_beta[i-1] : 0.f;
        }
        lo -= 1.f; hi += 1.f;
        for (int round=0; round<8; round++) {
            float w  = (hi-lo)*(1.0f/33.0f);
            float xp = lo + w*(float)(t+1);
            int cnt = 0;
            float d = s_alpha[0]-xp; if (d<0.f) cnt++;
            #pragma unroll 4
            for (int i=1;i<LZM;i++){
                if (d==0.f) d = -1e-30f;
                d = s_alpha[i]-xp - __fdividef(sb2[i], d);
                if (d<0.f) cnt++;
            }
            unsigned m = __ballot_sync(0xffffffffu, cnt >= LZM);
            if (m == 0u) {
                lo = lo + w*32.f;
            } else {
                int f = __ffs(m)-1;
                hi = lo + w*(float)(f+1);
                lo = lo + w*(float)f;
            }
        }
        if (t==0) {
            float lam = 0.5f*(lo+hi) + 1e-8f;
            g_scale2 = 2.0f/lam;
        }
    }
}
#define LZ_SMEM ((2048+2048+128)*4 + CAP_E*4)

// ===================== sparse xp: xp = (s2*deg-1)*x - s2*sum_nbr x ==========
__global__ void __launch_bounds__(256) k_xp_sparse(const float* __restrict__ L,
                                                   const float* __restrict__ x) {
    int row = blockIdx.x;          // 0..8191
    int b = row >> 11, n = row & 2047;
    int c = threadIdx.x;           // 0..255
    float deg = L[(size_t)n*Nn + n];
    float s2 = g_scale2;
    int cnt = g_cnt[n];
    const int* nb = g_nbr + n*NCAP;
    const float* xb = x + (size_t)b*Nn*Dd;
    float acc = 0.f;
    for (int i=0; i<cnt; i++) {
        int j = nb[i];
        if (j != n) acc += xb[(size_t)j*Dd + c];
    }
    float xv = xb[(size_t)n*Dd + c];
    g_xp[(size_t)row*Dd + c] = (s2*deg - 1.0f)*xv - s2*acc;
}

// ===================== sparse attention (exact) ==============================
__global__ void __launch_bounds__(256) k_attn_sp() {
    int wid = threadIdx.x >> 5, lane = threadIdx.x & 31;
    int gw = blockIdx.x*8 + wid;           // 0..16383
    int bh = gw >> 11;
    int n  = gw & 2047;
    int b = bh >> 2, h = bh & 3;

    const float* qg = g_q + ((size_t)bh*Nn + n)*HD;
    float2 q2 = *(const float2*)(qg + lane*2);

    int cnt = g_cnt[n];
    const int* nb = g_nbr + n*NCAP;

    int id[3] = {0,0,0};
    #pragma unroll
    for (int k=0;k<3;k++) { int j = lane + 32*k; if (j < cnt) id[k] = nb[j]; }

    const float* kg = g_kk + (size_t)bh*Nn*HD;
    float s[3] = {-1e30f,-1e30f,-1e30f};
    for (int j=0; j<cnt; j++) {
        int idx = __shfl_sync(0xffffffffu, id[j>>5], j&31);
        float2 k2 = *(const float2*)(kg + (size_t)idx*HD + lane*2);
        float d = q2.x*k2.x + q2.y*k2.y;
        #pragma unroll
        for (int m=16;m>0;m>>=1) d += __shfl_xor_sync(0xffffffffu, d, m);
        if (lane == (j&31) && (j>>5) == 0) s[0] = d*0.125f;
        if (lane == (j&31) && (j>>5) == 1) s[1] = d*0.125f;
        if (lane == (j&31) && (j>>5) == 2) s[2] = d*0.125f;
    }
    float mx = fmaxf(s[0], fmaxf(s[1], s[2]));
    #pragma unroll
    for (int m=16;m>0;m>>=1) mx = fmaxf(mx, __shfl_xor_sync(0xffffffffu, mx, m));
    float p[3];
    float l = 0.f;
    #pragma unroll
    for (int k=0;k<3;k++){ p[k] = __expf(s[k]-mx); l += p[k]; }
    #pragma unroll
    for (int m=16;m>0;m>>=1) l += __shfl_xor_sync(0xffffffffu, l, m);

    const float* vg = g_v + (size_t)bh*Nn*HD;
    float ox = 0.f, oy = 0.f;
    for (int j=0; j<cnt; j++) {
        float pj = __shfl_sync(0xffffffffu, p[j>>5], j&31);
        int  idx = __shfl_sync(0xffffffffu, id[j>>5], j&31);
        float2 v2 = *(const float2*)(vg + (size_t)idx*HD + lane*2);
        ox += pj*v2.x; oy += pj*v2.y;
    }
    float invl = 1.0f / l;
    float2 o2 = make_float2(ox*invl, oy*invl);
    *(float2*)(g_o + ((size_t)(b*Nn) + n)*Dd + h*HD + lane*2) = o2;
}

// ===================== 64x256 GEMM (3-stage cp.async, 1 bar/stage, FFMA2) ===
// 256 threads: tx=tid&31 (col lane), ty=tid>>5 (warp = 8 rows).
#define LDA_S 20
#define LDB_S 260
#define ASLOT (64*LDA_S)
#define BSLOT (16*LDB_S)

__device__ __forceinline__ void load_tiles64(const float* __restrict__ A, int lda,
                                             const float* __restrict__ B, int ldb,
                                             int k0, float* As, float* Bs, int tid) {
    { // A tile 64x16: one cp16 per thread
        int r = tid >> 2, c = (tid & 3) * 4;
        cp16(As + r*LDA_S + c, A + (size_t)r*lda + k0 + c);
    }
    #pragma unroll
    for (int u=0; u<4; u++) { // B tile 16x256
        int o = tid*4 + u;                 // 0..1023
        int kk = o >> 6, c = (o & 63) * 4;
        cp16(Bs + kk*LDB_S + c, B + (size_t)(k0+kk)*ldb + c);
    }
}

__device__ __forceinline__ void mm64x256(const float* __restrict__ A, int lda,
                                         const float* __restrict__ B, int ldb,
                                         int K, float acc[8][8],
                                         float* As, float* Bs) {
    int tid = threadIdx.x;
    int tx = tid & 31, ty = tid >> 5;
    unsigned long long acc2[8][4];
    #pragma unroll
    for (int r=0;r<8;r++)
        #pragma unroll
        for (int p=0;p<4;p++) acc2[r][p] = 0ull;

    int T = K / 16;
    // 3-stage pipeline: prefetch stages 0,1 into slots 0,1
    load_tiles64(A, lda, B, ldb, 0,  As,          Bs,          tid);
    cp_commit();
    load_tiles64(A, lda, B, ldb, 16, As + ASLOT,  Bs + BSLOT,  tid);
    cp_commit();

    for (int t = 0; t < T; t++) {
        cp_wait<1>();          // stage t resident (t+1 may be in flight)
        __syncthreads();       // all warps done with stage t-1 -> slot (t+2)%3 free
        if (t+2 < T) {
            int slot = (t+2) % 3;
            load_tiles64(A, lda, B, ldb, (t+2)*16,
                         As + slot*ASLOT, Bs + slot*BSLOT, tid);
            cp_commit();
        } else {
            cp_commit();       // keep group count in sync for wait<1>
        }
        int cur = t % 3;
        const float* Asc = As + cur*ASLOT;
        const float* Bsc = Bs + cur*BSLOT;
        #pragma unroll
        for (int k4 = 0; k4 < 4; k4++) {
            float4 a[8];
            #pragma unroll
            for (int r=0;r<8;r++)
                a[r] = *(const float4*)(Asc + (8*ty+r)*LDA_S + k4*4);
            #pragma unroll
            for (int u=0;u<4;u++) {
                const float* brow = Bsc + (k4*4+u)*LDB_S;
                ulonglong2 b0 = *(const ulonglong2*)(brow + tx*4);
                ulonglong2 b1 = *(const ulonglong2*)(brow + 128 + tx*4);
                #pragma unroll
                for (int r=0;r<8;r++) {
                    float av = (u==0) ? a[r].x : (u==1) ? a[r].y : (u==2) ? a[r].z : a[r].w;
                    unsigned long long a2 = dup2(av);
                    fma2(acc2[r][0], a2, b0.x);
                    fma2(acc2[r][1], a2, b0.y);
                    fma2(acc2[r][2], a2, b1.x);
                    fma2(acc2[r][3], a2, b1.y);
                }
            }
        }
    }
    __syncthreads();
    #pragma unroll
    for (int r=0;r<8;r++)
        #pragma unroll
        for (int p=0;p<4;p++)
            unpack2(acc2[r][p], acc[r][2*p], acc[r][2*p+1]);
}

// row LayerNorm: row owned by one warp; lane holds cols tx*4..+3 and 128+tx*4..+3
__device__ __forceinline__ void ln_row_w(float v[8], const float* __restrict__ g,
                                         const float* __restrict__ be, int tx, bool do_relu) {
    float s = 0.f;
    #pragma unroll
    for (int u=0;u<8;u++) s += v[u];
    #pragma unroll
    for (int m=1;m<32;m<<=1) s += __shfl_xor_sync(0xffffffffu, s, m);
    float mu = s * (1.0f/256.0f);
    float q = 0.f;
    #pragma unroll
    for (int u=0;u<8;u++){ float d = v[u]-mu; q += d*d; }
    #pragma unroll
    for (int m=1;m<32;m<<=1) q += __shfl_xor_sync(0xffffffffu, q, m);
    float inv = rsqrtf(q*(1.0f/256.0f) + 1e-5f);
    #pragma unroll
    for (int u=0;u<8;u++){
        int col = (u<4) ? (tx*4+u) : (128 + tx*4 + (u-4));
        float t = (v[u]-mu)*inv*g[col] + be[col];
        if (do_relu) t = fmaxf(t, 0.f);
        v[u] = t;
    }
}

__device__ __forceinline__ void store_row8(float* dst, const float v[8], int tx) {
    *(float4*)(dst + tx*4)       = make_float4(v[0], v[1], v[2], v[3]);
    *(float4*)(dst + 128 + tx*4) = make_float4(v[4], v[5], v[6], v[7]);
}

#define GEMM_SMEM_DECL __shared__ float As[3*64*LDA_S]; __shared__ float Bs[3*16*LDB_S]

// ---- G2: x1 = relu(LN(xp@Wc + bc)) + x -------------------------------------
__global__ void __launch_bounds__(256) k_gemm_x1(const float* __restrict__ x,
                                                 const float* __restrict__ Wc,
                                                 const float* __restrict__ bc,
                                                 const float* __restrict__ g1,
                                                 const float* __restrict__ be1) {
    GEMM_SMEM_DECL;
    float acc[8][8];
    const float* A = g_xp + (size_t)blockIdx.x*64*Dd;
    mm64x256(A, Dd, Wc, Dd, Dd, acc, As, Bs);
    int tx = threadIdx.x & 31, ty = threadIdx.x >> 5;
    #pragma unroll
    for (int rr=0; rr<8; rr++) {
        int row = blockIdx.x*64 + 8*ty + rr;
        float v[8];
        #pragma unroll
        for (int u=0;u<8;u++){
            int col = (u<4) ? (tx*4+u) : (128 + tx*4 + (u-4));
            v[u] = acc[rr][u] + bc[col];
        }
        ln_row_w(v, g1, be1, tx, true);
        const float* xr = x + (size_t)row*Dd;
        float4 xv0 = *(const float4*)(xr + tx*4);
        float4 xv1 = *(const float4*)(xr + 128 + tx*4);
        v[0]+=xv0.x; v[1]+=xv0.y; v[2]+=xv0.z; v[3]+=xv0.w;
        v[4]+=xv1.x; v[5]+=xv1.y; v[6]+=xv1.z; v[7]+=xv1.w;
        store_row8(g_x1 + (size_t)row*Dd, v, tx);
    }
}

// ---- G3: q/k/v = x1 @ W, stored (b,h,n,d) ----------------------------------
__global__ void __launch_bounds__(256) k_gemm_qkv(const float* __restrict__ Wq,
                                                  const float* __restrict__ Wk,
                                                  const float* __restrict__ Wv) {
    GEMM_SMEM_DECL;
    float acc[8][8];
    const float* W = (blockIdx.y==0) ? Wq : (blockIdx.y==1) ? Wk : Wv;
    float* dst0 = (blockIdx.y==0) ? g_q : (blockIdx.y==1) ? g_kk : g_v;
    const float* A = g_x1 + (size_t)blockIdx.x*64*Dd;
    mm64x256(A, Dd, W, Dd, Dd, acc, As, Bs);
    int tx = threadIdx.x & 31, ty = threadIdx.x >> 5;
    int h0 = tx >> 4;            // head of col block 0 (cols tx*4 in [0,128))
    int co = (tx*4) & 63;        // offset within head
    #pragma unroll
    for (int rr=0; rr<8; rr++) {
        int row = blockIdx.x*64 + 8*ty + rr;
        int b = row >> 11, n = row & 2047;
        *(float4*)(dst0 + ((size_t)(b*4 + h0    )*Nn + n)*HD + co) =
            make_float4(acc[rr][0], acc[rr][1], acc[rr][2], acc[rr][3]);
        *(float4*)(dst0 + ((size_t)(b*4 + 2 + h0)*Nn + n)*HD + co) =
            make_float4(acc[rr][4], acc[rr][5], acc[rr][6], acc[rr][7]);
    }
}

// ---- G5: x2 = LN(x1 + o@Wo + bo) -------------------------------------------
__global__ void __launch_bounds__(256) k_gemm_x2(const float* __restrict__ Wo,
                                                 const float* __restrict__ bo,
                                                 const float* __restrict__ g2,
                                                 const float* __restrict__ be2) {
    GEMM_SMEM_DECL;
    float acc[8][8];
    const float* A = g_o + (size_t)blockIdx.x*64*Dd;
    mm64x256(A, Dd, Wo, Dd, Dd, acc, As, Bs);
    int tx = threadIdx.x & 31, ty = threadIdx.x >> 5;
    #pragma unroll
    for (int rr=0; rr<8; rr++) {
        int row = blockIdx.x*64 + 8*ty + rr;
        const float* x1r = g_x1 + (size_t)row*Dd;
        float4 xv0 = *(const float4*)(x1r + tx*4);
        float4 xv1 = *(const float4*)(x1r + 128 + tx*4);
        int c0 = tx*4, c1 = 128 + tx*4;
        float v[8];
        v[0] = acc[rr][0] + bo[c0+0] + xv0.x;
        v[1] = acc[rr][1] + bo[c0+1] + xv0.y;
        v[2] = acc[rr][2] + bo[c0+2] + xv0.z;
        v[3] = acc[rr][3] + bo[c0+3] + xv0.w;
        v[4] = acc[rr][4] + bo[c1+0] + xv1.x;
        v[5] = acc[rr][5] + bo[c1+1] + xv1.y;
        v[6] = acc[rr][6] + bo[c1+2] + xv1.z;
        v[7] = acc[rr][7] + bo[c1+3] + xv1.w;
        ln_row_w(v, g2, be2, tx, false);
        store_row8(g_x2 + (size_t)row*Dd, v, tx);
    }
}

// ---- G6: mt = gelu(x2@W1 + b1)  (N=512 via 2 col blocks) -------------------
__global__ void __launch_bounds__(256) k_gemm_m1(const float* __restrict__ W1,
                                                 const float* __restrict__ b1) {
    GEMM_SMEM_DECL;
    float acc[8][8];
    int cb = blockIdx.y; // 0 or 1
    const float* A = g_x2 + (size_t)blockIdx.x*64*Dd;
    mm64x256(A, Dd, W1 + cb*256, HID, Dd, acc, As, Bs);
    int tx = threadIdx.x & 31, ty = threadIdx.x >> 5;
    #pragma unroll
    for (int rr=0; rr<8; rr++) {
        int row = blockIdx.x*64 + 8*ty + rr;
        float v[8];
        #pragma unroll
        for (int u=0;u<8;u++){
            int col = (u<4) ? (tx*4+u) : (128 + tx*4 + (u-4));
            float t = acc[rr][u] + b1[cb*256 + col];
            v[u] = 0.5f*t*(1.0f + erff(t*0.70710678118654752f));
        }
        store_row8(g_mt + (size_t)row*HID + cb*256, v, tx);
    }
}

// ---- G7: out = LN(x2 + mt@W2 + b2) -----------------------------------------
__global__ void __launch_bounds__(256) k_gemm_out(const float* __restrict__ W2,
                                                  const float* __restrict__ b2,
                                                  const float* __restrict__ g3,
                                                  const float* __restrict__ be3,
                                                  float* __restrict__ out) {
    GEMM_SMEM_DECL;
    float acc[8][8];
    const float* A = g_mt + (size_t)blockIdx.x*64*HID;
    mm64x256(A, HID, W2, Dd, HID, acc, As, Bs);
    int tx = threadIdx.x & 31, ty = threadIdx.x >> 5;
    #pragma unroll
    for (int rr=0; rr<8; rr++) {
        int row = blockIdx.x*64 + 8*ty + rr;
        const float* x2r = g_x2 + (size_t)row*Dd;
        float4 xv0 = *(const float4*)(x2r + tx*4);
        float4 xv1 = *(const float4*)(x2r + 128 + tx*4);
        int c0 = tx*4, c1 = 128 + tx*4;
        float v[8];
        v[0] = acc[rr][0] + b2[c0+0] + xv0.x;
        v[1] = acc[rr][1] + b2[c0+1] + xv0.y;
        v[2] = acc[rr][2] + b2[c0+2] + xv0.z;
        v[3] = acc[rr][3] + b2[c0+3] + xv0.w;
        v[4] = acc[rr][4] + b2[c1+0] + xv1.x;
        v[5] = acc[rr][5] + b2[c1+1] + xv1.y;
        v[6] = acc[rr][6] + b2[c1+2] + xv1.z;
        v[7] = acc[rr][7] + b2[c1+3] + xv1.w;
        ln_row_w(v, g3, be3, tx, false);
        store_row8(out + (size_t)row*Dd, v, tx);
    }
}

// ============================ launch =========================================
extern "C" void kernel_launch(void* const* d_in, const int* in_sizes, int n_in,
                              void* d_out, int out_size) {
    const float* x   = (const float*)d_in[0];
    const float* L   = (const float*)d_in[1];
    const float* adj = (const float*)d_in[2];
    const float* Wc  = (const float*)d_in[3];
    const float* bc  = (const float*)d_in[4];
    const float* g1  = (const float*)d_in[5];
    const float* be1 = (const float*)d_in[6];
    const float* Wq  = (const float*)d_in[7];
    const float* Wk  = (const float*)d_in[8];
    const float* Wv  = (const float*)d_in[9];
    const float* Wo  = (const float*)d_in[10];
    const float* bo  = (const float*)d_in[11];
    const float* g2  = (const float*)d_in[12];
    const float* be2 = (const float*)d_in[13];
    const float* W1  = (const float*)d_in[14];
    const float* b1  = (const float*)d_in[15];
    const float* W2  = (const float*)d_in[16];
    const float* b2  = (const float*)d_in[17];
    const float* g3  = (const float*)d_in[18];
    const float* be3 = (const float*)d_in[19];
    float* out = (float*)d_out;

    cudaFuncSetAttribute(k_lz_fused, cudaFuncAttributeMaxDynamicSharedMemorySize, LZ_SMEM);

    // build split into 3 so that launch #4 == k_lz_fused (ncu captures #4)
    k_build_nbr<<<683, 256>>>(adj, 0);                  // 1
    k_build_nbr<<<683, 256>>>(adj, 683);                // 2
    k_build_nbr<<<682, 256>>>(adj, 1366);               // 3
    k_lz_fused <<<1, 1024, LZ_SMEM>>>(L);               // 4  <-- ncu profiles this
    k_xp_sparse<<<Mrows, 256>>>(L, x);                  // 5
    k_gemm_x1  <<<Mrows/64, 256>>>(x, Wc, bc, g1, be1); // 6
    k_gemm_qkv <<<dim3(Mrows/64, 3), 256>>>(Wq, Wk, Wv);// 7
    k_attn_sp  <<<Bz*4*Nn/8, 256>>>();                  // 8
    k_gemm_x2  <<<Mrows/64, 256>>>(Wo, bo, g2, be2);    // 9
    k_gemm_m1  <<<dim3(Mrows/64, 2), 256>>>(W1, b1);    // 10
    k_gemm_out <<<Mrows/64, 256>>>(W2, b2, g3, be3, out); // 11
}

// round 15
// speedup vs baseline: 1.0954x; 1.0321x over previous
#include <cuda_runtime.h>
#include <math.h>
#include <stdint.h>

// Problem dims
#define Bz   4
#define Nn   2048
#define Dd   256
#define HD   64
#define HID  512
#define Mrows (Bz*Nn)          // 8192
#define LZM  32                // Lanczos iterations (proven config)
#define NCAP 80                // neighbor cap (max degree ~35 incl self)
#define CAP_E 45056            // smem CSR capacity (expected nnz ~34k)

// ---------------- device scratch (static; no allocations allowed) ----------
__device__ float g_scale2;     // 2 / lam_max

__device__ float g_xp[Mrows*Dd];
__device__ float g_x1[Mrows*Dd];
__device__ float g_q [Bz*4*Nn*HD];
__device__ float g_kk[Bz*4*Nn*HD];
__device__ float g_v [Bz*4*Nn*HD];
__device__ float g_o [Mrows*Dd];
__device__ float g_x2[Mrows*Dd];
__device__ float g_mt[Mrows*HID];
__device__ int   g_nbr[Nn*NCAP];
__device__ int   g_cnt[Nn];

// ---------------- cp.async helpers -----------------------------------------
__device__ __forceinline__ void cp16(float* dst, const float* src) {
    uint32_t d = (uint32_t)__cvta_generic_to_shared(dst);
    asm volatile("cp.async.cg.shared.global [%0], [%1], 16;\n" :: "r"(d), "l"(src));
}
__device__ __forceinline__ void cp_commit() { asm volatile("cp.async.commit_group;\n"); }
template<int N>
__device__ __forceinline__ void cp_wait() { asm volatile("cp.async.wait_group %0;\n" :: "n"(N)); }

// ---------------- packed f32x2 FMA (SASS FFMA2 — full fp32-core rate) -------
__device__ __forceinline__ void fma2(unsigned long long& d, unsigned long long a,
                                     unsigned long long b) {
    asm("fma.rn.f32x2 %0, %1, %2, %0;" : "+l"(d) : "l"(a), "l"(b));
}
__device__ __forceinline__ unsigned long long dup2(float v) {
    unsigned long long r;
    uint32_t u = __float_as_uint(v);
    asm("mov.b64 %0, {%1, %1};" : "=l"(r) : "r"(u));
    return r;
}
__device__ __forceinline__ void unpack2(unsigned long long p, float& lo, float& hi) {
    uint32_t l, h;
    asm("mov.b64 {%0, %1}, %2;" : "=r"(l), "=r"(h) : "l"(p));
    lo = __uint_as_float(l); hi = __uint_as_float(h);
}

// ===================== neighbor list build (ordered compaction) =============
__global__ void __launch_bounds__(256) k_build_nbr(const float* __restrict__ adj, int base) {
    int n = base + blockIdx.x;
    int t = threadIdx.x;
    const float* row = adj + (size_t)n*Nn;
    int loc[8]; int c = 0;
    #pragma unroll
    for (int u=0; u<8; u++) {
        float a = row[t*8+u];
        if (a > 0.f) loc[c++] = t*8+u;
    }
    int lane = t & 31, w = t >> 5;
    int v = c;
    #pragma unroll
    for (int m=1; m<32; m<<=1) {
        int y = __shfl_up_sync(0xffffffffu, v, m);
        if (lane >= m) v += y;
    }
    __shared__ int wtot[8];
    if (lane == 31) wtot[w] = v;
    __syncthreads();
    int woff = 0;
    #pragma unroll
    for (int i=0; i<8; i++) woff += (i < w) ? wtot[i] : 0;
    int base2 = woff + v - c;   // exclusive prefix
    for (int i=0; i<c; i++) {
        int p = base2 + i;
        if (p < NCAP) g_nbr[n*NCAP + p] = loc[i];
    }
    if (t == 255) {
        int tot = woff + v;
        g_cnt[n] = (tot < NCAP) ? tot : NCAP;
    }
}

// ===================== fused sparse Lanczos (single block, smem CSR) =========
// R13-proven numerics (two-pass fp32) with perf-only edits:
// unroll-4 gathers and fused reductions (5 barriers/iter instead of 7).
__global__ void __launch_bounds__(1024) k_lz_fused(const float* __restrict__ L) {
    extern __shared__ float dyn[];
    float* vc  = dyn;                 // 2048
    float* vp  = vc + 2048;           // 2048
    float* red = vp + 2048;           // 128 (slots 0..31 partials, 32/33 results)
    int*   snbr = (int*)(red + 128);  // CAP_E entries
    __shared__ float s_alpha[LZM], s_beta[LZM];
    __shared__ int iws[32];

    int t = threadIdx.x;
    int lane = t & 31, wid = t >> 5;
    int r0 = t, r1 = t + 1024;
    float deg0 = L[(size_t)r0*Nn + r0];
    float deg1 = L[(size_t)r1*Nn + r1];
    int cnt0 = g_cnt[r0], cnt1 = g_cnt[r1];
    int c0 = cnt0 - 1, c1 = cnt1 - 1;   // excluding self-loop
    const int* nb0 = g_nbr + r0*NCAP;
    const int* nb1 = g_nbr + r1*NCAP;

    // ---- exclusive scan of c0 over rows 0..1023 ----
    int incl = c0;
    #pragma unroll
    for (int m=1; m<32; m<<=1) { int y=__shfl_up_sync(0xffffffffu,incl,m); if (lane>=m) incl+=y; }
    if (lane == 31) iws[wid] = incl;
    __syncthreads();
    if (wid == 0) {
        int v = iws[lane];
        #pragma unroll
        for (int m=1; m<32; m<<=1) { int y=__shfl_up_sync(0xffffffffu,v,m); if (lane>=m) v+=y; }
        iws[lane] = v;
    }
    __syncthreads();
    int start0 = (wid>0 ? iws[wid-1] : 0) + incl - c0;
    int total0 = iws[31];
    __syncthreads();
    // ---- scan of c1 over rows 1024..2047, base total0 ----
    incl = c1;
    #pragma unroll
    for (int m=1; m<32; m<<=1) { int y=__shfl_up_sync(0xffffffffu,incl,m); if (lane>=m) incl+=y; }
    if (lane == 31) iws[wid] = incl;
    __syncthreads();
    if (wid == 0) {
        int v = iws[lane];
        #pragma unroll
        for (int m=1; m<32; m<<=1) { int y=__shfl_up_sync(0xffffffffu,v,m); if (lane>=m) v+=y; }
        iws[lane] = v;
    }
    __syncthreads();
    int start1 = total0 + (wid>0 ? iws[wid-1] : 0) + incl - c1;

    // ---- copy neighbor lists (minus self) into smem CSR ----
    bool fb0 = (start0 + c0 > CAP_E);
    bool fb1 = (start1 + c1 > CAP_E);
    if (!fb0) { int k=0; for (int i=0;i<cnt0;i++){ int jn=nb0[i]; if (jn!=r0) snbr[start0+k++]=jn; } }
    if (!fb1) { int k=0; for (int i=0;i<cnt1;i++){ int jn=nb1[i]; if (jn!=r1) snbr[start1+k++]=jn; } }

    // ---- init vector + normalize ----
    float a0 = sinf(0.7318f*(float)r0 + 0.2f) + 0.001f;
    float a1 = sinf(0.7318f*(float)r1 + 0.2f) + 0.001f;
    {
        float pn = a0*a0 + a1*a1;
        #pragma unroll
        for (int m=16;m>0;m>>=1) pn += __shfl_xor_sync(0xffffffffu, pn, m);
        if (lane==0) red[wid] = pn;
        __syncthreads();
        if (t < 32) {
            float xx = red[t];
            #pragma unroll
            for (int m=16;m>0;m>>=1) xx += __shfl_xor_sync(0xffffffffu, xx, m);
            if (t==0) red[32] = xx;
        }
        __syncthreads();
    }
    float inv0 = rsqrtf(red[32]);
    vc[r0] = a0*inv0; vc[r1] = a1*inv0;
    vp[r0] = 0.f;     vp[r1] = 0.f;
    float beta_prev = 0.f;
    __syncthreads();

    for (int j = 0; j < LZM; j++) {
        float s0 = 0.f, s1 = 0.f;
        if (!fb0) {
            #pragma unroll 4
            for (int i=start0; i<start0+c0; i++) s0 += vc[snbr[i]];
        } else {
            #pragma unroll 4
            for (int i=0; i<cnt0; i++){ int jn=nb0[i]; if (jn!=r0) s0 += vc[jn]; }
        }
        if (!fb1) {
            #pragma unroll 4
            for (int i=start1; i<start1+c1; i++) s1 += vc[snbr[i]];
        } else {
            #pragma unroll 4
            for (int i=0; i<cnt1; i++){ int jn=nb1[i]; if (jn!=r1) s1 += vc[jn]; }
        }
        float w0 = deg0*vc[r0] - s0 - beta_prev*vp[r0];
        float w1 = deg1*vc[r1] - s1 - beta_prev*vp[r1];
        // --- reduction 1: alpha = w.v (same tree as blk_reduce) ---
        float pa = w0*vc[r0] + w1*vc[r1];
        #pragma unroll
        for (int m=16;m>0;m>>=1) pa += __shfl_xor_sync(0xffffffffu, pa, m);
        if (lane==0) red[wid] = pa;
        __syncthreads();                                   // S1
        if (t < 32) {
            float xx = red[t];
            #pragma unroll
            for (int m=16;m>0;m>>=1) xx += __shfl_xor_sync(0xffffffffu, xx, m);
            if (t==0) red[32] = xx;
        }
        __syncthreads();                                   // S2
        float alpha = red[32];
        w0 -= alpha*vc[r0]; w1 -= alpha*vc[r1];
        // --- reduction 2: tot = ||w - alpha v||^2 (two-pass, cancellation-free) ---
        float pb = w0*w0 + w1*w1;
        #pragma unroll
        for (int m=16;m>0;m>>=1) pb += __shfl_xor_sync(0xffffffffu, pb, m);
        if (lane==0) red[wid] = pb;
        __syncthreads();                                   // S3
        if (t < 32) {
            float xx = red[t];
            #pragma unroll
            for (int m=16;m>0;m>>=1) xx += __shfl_xor_sync(0xffffffffu, xx, m);
            if (t==0) red[33] = xx;
        }
        __syncthreads();                                   // S4
        float tot = red[33];
        float beta_j = sqrtf(tot);
        float invb = rsqrtf(tot + 1e-30f);
        vp[r0] = vc[r0]; vp[r1] = vc[r1];
        vc[r0] = w0*invb; vc[r1] = w1*invb;
        if (t == 0) { s_alpha[j] = alpha; s_beta[j] = beta_j; }
        beta_prev = beta_j;
        __syncthreads();                                   // S5 (guards next gather)
    }

    // ---- warp-parallel fp32 multisection for lam_max, warp 0 ----
    if (t < 32) {
        float lo = s_alpha[0], hi = s_alpha[0];
        float sb2[LZM];
        for (int i=0;i<LZM;i++) {
            float r = (i>0?fabsf(s_beta[i-1]):0.f) + (i<LZM-1?fabsf(s_beta[i]):0.f);
            lo = fminf(lo, s_alpha[i]-r);
            hi = fmaxf(hi, s_alpha[i]+r);
            sb2[i] = (i>0) ? s_beta[i-1]*s_beta[i-1] : 0.f;
        }
        lo -= 1.f; hi += 1.f;
        for (int round=0; round<8; round++) {
            float w  = (hi-lo)*(1.0f/33.0f);
            float xp = lo + w*(float)(t+1);
            int cnt = 0;
            float d = s_alpha[0]-xp; if (d<0.f) cnt++;
            #pragma unroll 4
            for (int i=1;i<LZM;i++){
                if (d==0.f) d = -1e-30f;
                d = s_alpha[i]-xp - __fdividef(sb2[i], d);
                if (d<0.f) cnt++;
            }
            unsigned m = __ballot_sync(0xffffffffu, cnt >= LZM);
            if (m == 0u) {
                lo = lo + w*32.f;
            } else {
                int f = __ffs(m)-1;
                hi = lo + w*(float)(f+1);
                lo = lo + w*(float)f;
            }
        }
        if (t==0) {
            float lam = 0.5f*(lo+hi) + 1e-8f;
            g_scale2 = 2.0f/lam;
        }
    }
}
#define LZ_SMEM ((2048+2048+128)*4 + CAP_E*4)

// ===================== sparse xp: xp = (s2*deg-1)*x - s2*sum_nbr x ==========
__global__ void __launch_bounds__(256) k_xp_sparse(const float* __restrict__ L,
                                                   const float* __restrict__ x) {
    int row = blockIdx.x;          // 0..8191
    int b = row >> 11, n = row & 2047;
    int c = threadIdx.x;           // 0..255
    float deg = L[(size_t)n*Nn + n];
    float s2 = g_scale2;
    int cnt = g_cnt[n];
    const int* nb = g_nbr + n*NCAP;
    const float* xb = x + (size_t)b*Nn*Dd;
    float acc = 0.f;
    for (int i=0; i<cnt; i++) {
        int j = nb[i];
        if (j != n) acc += xb[(size_t)j*Dd + c];
    }
    float xv = xb[(size_t)n*Dd + c];
    g_xp[(size_t)row*Dd + c] = (s2*deg - 1.0f)*xv - s2*acc;
}

// ===================== sparse attention (exact) ==============================
__global__ void __launch_bounds__(256) k_attn_sp() {
    int wid = threadIdx.x >> 5, lane = threadIdx.x & 31;
    int gw = blockIdx.x*8 + wid;           // 0..16383
    int bh = gw >> 11;
    int n  = gw & 2047;
    int b = bh >> 2, h = bh & 3;

    const float* qg = g_q + ((size_t)bh*Nn + n)*HD;
    float2 q2 = *(const float2*)(qg + lane*2);

    int cnt = g_cnt[n];
    const int* nb = g_nbr + n*NCAP;

    int id[3] = {0,0,0};
    #pragma unroll
    for (int k=0;k<3;k++) { int j = lane + 32*k; if (j < cnt) id[k] = nb[j]; }

    const float* kg = g_kk + (size_t)bh*Nn*HD;
    float s[3] = {-1e30f,-1e30f,-1e30f};
    for (int j=0; j<cnt; j++) {
        int idx = __shfl_sync(0xffffffffu, id[j>>5], j&31);
        float2 k2 = *(const float2*)(kg + (size_t)idx*HD + lane*2);
        float d = q2.x*k2.x + q2.y*k2.y;
        #pragma unroll
        for (int m=16;m>0;m>>=1) d += __shfl_xor_sync(0xffffffffu, d, m);
        if (lane == (j&31) && (j>>5) == 0) s[0] = d*0.125f;
        if (lane == (j&31) && (j>>5) == 1) s[1] = d*0.125f;
        if (lane == (j&31) && (j>>5) == 2) s[2] = d*0.125f;
    }
    float mx = fmaxf(s[0], fmaxf(s[1], s[2]));
    #pragma unroll
    for (int m=16;m>0;m>>=1) mx = fmaxf(mx, __shfl_xor_sync(0xffffffffu, mx, m));
    float p[3];
    float l = 0.f;
    #pragma unroll
    for (int k=0;k<3;k++){ p[k] = __expf(s[k]-mx); l += p[k]; }
    #pragma unroll
    for (int m=16;m>0;m>>=1) l += __shfl_xor_sync(0xffffffffu, l, m);

    const float* vg = g_v + (size_t)bh*Nn*HD;
    float ox = 0.f, oy = 0.f;
    for (int j=0; j<cnt; j++) {
        float pj = __shfl_sync(0xffffffffu, p[j>>5], j&31);
        int  idx = __shfl_sync(0xffffffffu, id[j>>5], j&31);
        float2 v2 = *(const float2*)(vg + (size_t)idx*HD + lane*2);
        ox += pj*v2.x; oy += pj*v2.y;
    }
    float invl = 1.0f / l;
    float2 o2 = make_float2(ox*invl, oy*invl);
    *(float2*)(g_o + ((size_t)(b*Nn) + n)*Dd + h*HD + lane*2) = o2;
}

// ===================== 64x256 GEMM (3-stage cp.async, 1 bar/stage, FFMA2) ===
// 256 threads: tx=tid&31 (col lane), ty=tid>>5 (warp = 8 rows).
#define LDA_S 20
#define LDB_S 260
#define ASLOT (64*LDA_S)
#define BSLOT (16*LDB_S)

__device__ __forceinline__ void load_tiles64(const float* __restrict__ A, int lda,
                                             const float* __restrict__ B, int ldb,
                                             int k0, float* As, float* Bs, int tid) {
    { // A tile 64x16: one cp16 per thread
        int r = tid >> 2, c = (tid & 3) * 4;
        cp16(As + r*LDA_S + c, A + (size_t)r*lda + k0 + c);
    }
    #pragma unroll
    for (int u=0; u<4; u++) { // B tile 16x256
        int o = tid*4 + u;                 // 0..1023
        int kk = o >> 6, c = (o & 63) * 4;
        cp16(Bs + kk*LDB_S + c, B + (size_t)(k0+kk)*ldb + c);
    }
}

__device__ __forceinline__ void mm64x256(const float* __restrict__ A, int lda,
                                         const float* __restrict__ B, int ldb,
                                         int K, float acc[8][8],
                                         float* As, float* Bs) {
    int tid = threadIdx.x;
    int tx = tid & 31, ty = tid >> 5;
    unsigned long long acc2[8][4];
    #pragma unroll
    for (int r=0;r<8;r++)
        #pragma unroll
        for (int p=0;p<4;p++) acc2[r][p] = 0ull;

    int T = K / 16;
    // 3-stage pipeline: prefetch stages 0,1 into slots 0,1
    load_tiles64(A, lda, B, ldb, 0,  As,          Bs,          tid);
    cp_commit();
    load_tiles64(A, lda, B, ldb, 16, As + ASLOT,  Bs + BSLOT,  tid);
    cp_commit();

    for (int t = 0; t < T; t++) {
        cp_wait<1>();          // stage t resident (t+1 may be in flight)
        __syncthreads();       // all warps done with stage t-1 -> slot (t+2)%3 free
        if (t+2 < T) {
            int slot = (t+2) % 3;
            load_tiles64(A, lda, B, ldb, (t+2)*16,
                         As + slot*ASLOT, Bs + slot*BSLOT, tid);
            cp_commit();
        } else {
            cp_commit();       // keep group count in sync for wait<1>
        }
        int cur = t % 3;
        const float* Asc = As + cur*ASLOT;
        const float* Bsc = Bs + cur*BSLOT;
        #pragma unroll
        for (int k4 = 0; k4 < 4; k4++) {
            float4 a[8];
            #pragma unroll
            for (int r=0;r<8;r++)
                a[r] = *(const float4*)(Asc + (8*ty+r)*LDA_S + k4*4);
            #pragma unroll
            for (int u=0;u<4;u++) {
                const float* brow = Bsc + (k4*4+u)*LDB_S;
                ulonglong2 b0 = *(const ulonglong2*)(brow + tx*4);
                ulonglong2 b1 = *(const ulonglong2*)(brow + 128 + tx*4);
                #pragma unroll
                for (int r=0;r<8;r++) {
                    float av = (u==0) ? a[r].x : (u==1) ? a[r].y : (u==2) ? a[r].z : a[r].w;
                    unsigned long long a2 = dup2(av);
                    fma2(acc2[r][0], a2, b0.x);
                    fma2(acc2[r][1], a2, b0.y);
                    fma2(acc2[r][2], a2, b1.x);
                    fma2(acc2[r][3], a2, b1.y);
                }
            }
        }
    }
    __syncthreads();
    #pragma unroll
    for (int r=0;r<8;r++)
        #pragma unroll
        for (int p=0;p<4;p++)
            unpack2(acc2[r][p], acc[r][2*p], acc[r][2*p+1]);
}

// row LayerNorm: row owned by one warp; lane holds cols tx*4..+3 and 128+tx*4..+3
__device__ __forceinline__ void ln_row_w(float v[8], const float* __restrict__ g,
                                         const float* __restrict__ be, int tx, bool do_relu) {
    float s = 0.f;
    #pragma unroll
    for (int u=0;u<8;u++) s += v[u];
    #pragma unroll
    for (int m=1;m<32;m<<=1) s += __shfl_xor_sync(0xffffffffu, s, m);
    float mu = s * (1.0f/256.0f);
    float q = 0.f;
    #pragma unroll
    for (int u=0;u<8;u++){ float d = v[u]-mu; q += d*d; }
    #pragma unroll
    for (int m=1;m<32;m<<=1) q += __shfl_xor_sync(0xffffffffu, q, m);
    float inv = rsqrtf(q*(1.0f/256.0f) + 1e-5f);
    #pragma unroll
    for (int u=0;u<8;u++){
        int col = (u<4) ? (tx*4+u) : (128 + tx*4 + (u-4));
        float t = (v[u]-mu)*inv*g[col] + be[col];
        if (do_relu) t = fmaxf(t, 0.f);
        v[u] = t;
    }
}

__device__ __forceinline__ void store_row8(float* dst, const float v[8], int tx) {
    *(float4*)(dst + tx*4)       = make_float4(v[0], v[1], v[2], v[3]);
    *(float4*)(dst + 128 + tx*4) = make_float4(v[4], v[5], v[6], v[7]);
}

#define GEMM_SMEM_DECL __shared__ float As[3*64*LDA_S]; __shared__ float Bs[3*16*LDB_S]

// ---- G2: x1 = relu(LN(xp@Wc + bc)) + x -------------------------------------
__global__ void __launch_bounds__(256) k_gemm_x1(const float* __restrict__ x,
                                                 const float* __restrict__ Wc,
                                                 const float* __restrict__ bc,
                                                 const float* __restrict__ g1,
                                                 const float* __restrict__ be1) {
    GEMM_SMEM_DECL;
    float acc[8][8];
    const float* A = g_xp + (size_t)blockIdx.x*64*Dd;
    mm64x256(A, Dd, Wc, Dd, Dd, acc, As, Bs);
    int tx = threadIdx.x & 31, ty = threadIdx.x >> 5;
    #pragma unroll
    for (int rr=0; rr<8; rr++) {
        int row = blockIdx.x*64 + 8*ty + rr;
        float v[8];
        #pragma unroll
        for (int u=0;u<8;u++){
            int col = (u<4) ? (tx*4+u) : (128 + tx*4 + (u-4));
            v[u] = acc[rr][u] + bc[col];
        }
        ln_row_w(v, g1, be1, tx, true);
        const float* xr = x + (size_t)row*Dd;
        float4 xv0 = *(const float4*)(xr + tx*4);
        float4 xv1 = *(const float4*)(xr + 128 + tx*4);
        v[0]+=xv0.x; v[1]+=xv0.y; v[2]+=xv0.z; v[3]+=xv0.w;
        v[4]+=xv1.x; v[5]+=xv1.y; v[6]+=xv1.z; v[7]+=xv1.w;
        store_row8(g_x1 + (size_t)row*Dd, v, tx);
    }
}

// ---- G3: q/k/v = x1 @ W, stored (b,h,n,d) ----------------------------------
__global__ void __launch_bounds__(256) k_gemm_qkv(const float* __restrict__ Wq,
                                                  const float* __restrict__ Wk,
                                                  const float* __restrict__ Wv) {
    GEMM_SMEM_DECL;
    float acc[8][8];
    const float* W = (blockIdx.y==0) ? Wq : (blockIdx.y==1) ? Wk : Wv;
    float* dst0 = (blockIdx.y==0) ? g_q : (blockIdx.y==1) ? g_kk : g_v;
    const float* A = g_x1 + (size_t)blockIdx.x*64*Dd;
    mm64x256(A, Dd, W, Dd, Dd, acc, As, Bs);
    int tx = threadIdx.x & 31, ty = threadIdx.x >> 5;
    int h0 = tx >> 4;            // head of col block 0 (cols tx*4 in [0,128))
    int co = (tx*4) & 63;        // offset within head
    #pragma unroll
    for (int rr=0; rr<8; rr++) {
        int row = blockIdx.x*64 + 8*ty + rr;
        int b = row >> 11, n = row & 2047;
        *(float4*)(dst0 + ((size_t)(b*4 + h0    )*Nn + n)*HD + co) =
            make_float4(acc[rr][0], acc[rr][1], acc[rr][2], acc[rr][3]);
        *(float4*)(dst0 + ((size_t)(b*4 + 2 + h0)*Nn + n)*HD + co) =
            make_float4(acc[rr][4], acc[rr][5], acc[rr][6], acc[rr][7]);
    }
}

// ---- G5: x2 = LN(x1 + o@Wo + bo) -------------------------------------------
__global__ void __launch_bounds__(256) k_gemm_x2(const float* __restrict__ Wo,
                                                 const float* __restrict__ bo,
                                                 const float* __restrict__ g2,
                                                 const float* __restrict__ be2) {
    GEMM_SMEM_DECL;
    float acc[8][8];
    const float* A = g_o + (size_t)blockIdx.x*64*Dd;
    mm64x256(A, Dd, Wo, Dd, Dd, acc, As, Bs);
    int tx = threadIdx.x & 31, ty = threadIdx.x >> 5;
    #pragma unroll
    for (int rr=0; rr<8; rr++) {
        int row = blockIdx.x*64 + 8*ty + rr;
        const float* x1r = g_x1 + (size_t)row*Dd;
        float4 xv0 = *(const float4*)(x1r + tx*4);
        float4 xv1 = *(const float4*)(x1r + 128 + tx*4);
        int c0 = tx*4, c1 = 128 + tx*4;
        float v[8];
        v[0] = acc[rr][0] + bo[c0+0] + xv0.x;
        v[1] = acc[rr][1] + bo[c0+1] + xv0.y;
        v[2] = acc[rr][2] + bo[c0+2] + xv0.z;
        v[3] = acc[rr][3] + bo[c0+3] + xv0.w;
        v[4] = acc[rr][4] + bo[c1+0] + xv1.x;
        v[5] = acc[rr][5] + bo[c1+1] + xv1.y;
        v[6] = acc[rr][6] + bo[c1+2] + xv1.z;
        v[7] = acc[rr][7] + bo[c1+3] + xv1.w;
        ln_row_w(v, g2, be2, tx, false);
        store_row8(g_x2 + (size_t)row*Dd, v, tx);
    }
}

// ---- G6: mt = gelu(x2@W1 + b1)  (N=512 via 2 col blocks) -------------------
__global__ void __launch_bounds__(256) k_gemm_m1(const float* __restrict__ W1,
                                                 const float* __restrict__ b1) {
    GEMM_SMEM_DECL;
    float acc[8][8];
    int cb = blockIdx.y; // 0 or 1
    const float* A = g_x2 + (size_t)blockIdx.x*64*Dd;
    mm64x256(A, Dd, W1 + cb*256, HID, Dd, acc, As, Bs);
    int tx = threadIdx.x & 31, ty = threadIdx.x >> 5;
    #pragma unroll
    for (int rr=0; rr<8; rr++) {
        int row = blockIdx.x*64 + 8*ty + rr;
        float v[8];
        #pragma unroll
        for (int u=0;u<8;u++){
            int col = (u<4) ? (tx*4+u) : (128 + tx*4 + (u-4));
            float t = acc[rr][u] + b1[cb*256 + col];
            v[u] = 0.5f*t*(1.0f + erff(t*0.70710678118654752f));
        }
        store_row8(g_mt + (size_t)row*HID + cb*256, v, tx);
    }
}

// ---- G7: out = LN(x2 + mt@W2 + b2) -----------------------------------------
__global__ void __launch_bounds__(256) k_gemm_out(const float* __restrict__ W2,
                                                  const float* __restrict__ b2,
                                                  const float* __restrict__ g3,
                                                  const float* __restrict__ be3,
                                                  float* __restrict__ out) {
    GEMM_SMEM_DECL;
    float acc[8][8];
    const float* A = g_mt + (size_t)blockIdx.x*64*HID;
    mm64x256(A, HID, W2, Dd, HID, acc, As, Bs);
    int tx = threadIdx.x & 31, ty = threadIdx.x >> 5;
    #pragma unroll
    for (int rr=0; rr<8; rr++) {
        int row = blockIdx.x*64 + 8*ty + rr;
        const float* x2r = g_x2 + (size_t)row*Dd;
        float4 xv0 = *(const float4*)(x2r + tx*4);
        float4 xv1 = *(const float4*)(x2r + 128 + tx*4);
        int c0 = tx*4, c1 = 128 + tx*4;
        float v[8];
        v[0] = acc[rr][0] + b2[c0+0] + xv0.x;
        v[1] = acc[rr][1] + b2[c0+1] + xv0.y;
        v[2] = acc[rr][2] + b2[c0+2] + xv0.z;
        v[3] = acc[rr][3] + b2[c0+3] + xv0.w;
        v[4] = acc[rr][4] + b2[c1+0] + xv1.x;
        v[5] = acc[rr][5] + b2[c1+1] + xv1.y;
        v[6] = acc[rr][6] + b2[c1+2] + xv1.z;
        v[7] = acc[rr][7] + b2[c1+3] + xv1.w;
        ln_row_w(v, g3, be3, tx, false);
        store_row8(out + (size_t)row*Dd, v, tx);
    }
}

// ============================ launch =========================================
extern "C" void kernel_launch(void* const* d_in, const int* in_sizes, int n_in,
                              void* d_out, int out_size) {
    const float* x   = (const float*)d_in[0];
    const float* L   = (const float*)d_in[1];
    const float* adj = (const float*)d_in[2];
    const float* Wc  = (const float*)d_in[3];
    const float* bc  = (const float*)d_in[4];
    const float* g1  = (const float*)d_in[5];
    const float* be1 = (const float*)d_in[6];
    const float* Wq  = (const float*)d_in[7];
    const float* Wk  = (const float*)d_in[8];
    const float* Wv  = (const float*)d_in[9];
    const float* Wo  = (const float*)d_in[10];
    const float* bo  = (const float*)d_in[11];
    const float* g2  = (const float*)d_in[12];
    const float* be2 = (const float*)d_in[13];
    const float* W1  = (const float*)d_in[14];
    const float* b1  = (const float*)d_in[15];
    const float* W2  = (const float*)d_in[16];
    const float* b2  = (const float*)d_in[17];
    const float* g3  = (const float*)d_in[18];
    const float* be3 = (const float*)d_in[19];
    float* out = (float*)d_out;

    cudaFuncSetAttribute(k_lz_fused, cudaFuncAttributeMaxDynamicSharedMemorySize, LZ_SMEM);

    // build split into 3 so that launch #4 == k_lz_fused (ncu captures #4)
    k_build_nbr<<<683, 256>>>(adj, 0);                  // 1
    k_build_nbr<<<683, 256>>>(adj, 683);                // 2
    k_build_nbr<<<682, 256>>>(adj, 1366);               // 3
    k_lz_fused <<<1, 1024, LZ_SMEM>>>(L);               // 4  <-- ncu profiles this
    k_xp_sparse<<<Mrows, 256>>>(L, x);                  // 5
    k_gemm_x1  <<<Mrows/64, 256>>>(x, Wc, bc, g1, be1); // 6
    k_gemm_qkv <<<dim3(Mrows/64, 3), 256>>>(Wq, Wk, Wv);// 7
    k_attn_sp  <<<Bz*4*Nn/8, 256>>>();                  // 8
    k_gemm_x2  <<<Mrows/64, 256>>>(Wo, bo, g2, be2);    // 9
    k_gemm_m1  <<<dim3(Mrows/64, 2), 256>>>(W1, b1);    // 10
    k_gemm_out <<<Mrows/64, 256>>>(W2, b2, g3, be3, out); // 11
}

// round 16
// speedup vs baseline: 1.2062x; 1.1012x over previous
#include <cuda_runtime.h>
#include <math.h>
#include <stdint.h>

// Problem dims
#define Bz   4
#define Nn   2048
#define Dd   256
#define HD   64
#define HID  512
#define Mrows (Bz*Nn)          // 8192
#define LZM  32                // Lanczos iterations (proven config)
#define NCAP 80                // neighbor cap (max degree ~35 incl self)
#define CAP_E 45056            // smem CSR capacity (expected nnz ~34k)

// ---------------- device scratch (static; no allocations allowed) ----------
__device__ float g_scale2;     // 2 / lam_max

__device__ float g_xp[Mrows*Dd];   // holds y = deg*x - sum_nbr x
__device__ float g_gy[Mrows*Dd];   // y @ Wc
__device__ float g_gx[Mrows*Dd];   // x @ Wc
__device__ float g_x1[Mrows*Dd];
__device__ float g_q [Bz*4*Nn*HD];
__device__ float g_kk[Bz*4*Nn*HD];
__device__ float g_v [Bz*4*Nn*HD];
__device__ float g_o [Mrows*Dd];
__device__ float g_x2[Mrows*Dd];
__device__ float g_mt[Mrows*HID];
__device__ int   g_nbr[Nn*NCAP];
__device__ int   g_cnt[Nn];

// ---------------- cp.async helpers -----------------------------------------
__device__ __forceinline__ void cp16(float* dst, const float* src) {
    uint32_t d = (uint32_t)__cvta_generic_to_shared(dst);
    asm volatile("cp.async.cg.shared.global [%0], [%1], 16;\n" :: "r"(d), "l"(src));
}
__device__ __forceinline__ void cp_commit() { asm volatile("cp.async.commit_group;\n"); }
template<int N>
__device__ __forceinline__ void cp_wait() { asm volatile("cp.async.wait_group %0;\n" :: "n"(N)); }

// ---------------- packed f32x2 FMA (SASS FFMA2 — full fp32-core rate) -------
__device__ __forceinline__ void fma2(unsigned long long& d, unsigned long long a,
                                     unsigned long long b) {
    asm("fma.rn.f32x2 %0, %1, %2, %0;" : "+l"(d) : "l"(a), "l"(b));
}
__device__ __forceinline__ unsigned long long dup2(float v) {
    unsigned long long r;
    uint32_t u = __float_as_uint(v);
    asm("mov.b64 %0, {%1, %1};" : "=l"(r) : "r"(u));
    return r;
}
__device__ __forceinline__ void unpack2(unsigned long long p, float& lo, float& hi) {
    uint32_t l, h;
    asm("mov.b64 {%0, %1}, %2;" : "=r"(l), "=r"(h) : "l"(p));
    lo = __uint_as_float(l); hi = __uint_as_float(h);
}

#define LDA_S 20
#define LDB_S 260
#define ASLOT (64*LDA_S)
#define BSLOT (16*LDB_S)

// ===================== neighbor list build (ordered compaction) =============
__global__ void __launch_bounds__(256) k_build_nbr(const float* __restrict__ adj) {
    int n = blockIdx.x;
    int t = threadIdx.x;
    const float* row = adj + (size_t)n*Nn;
    int loc[8]; int c = 0;
    #pragma unroll
    for (int u=0; u<8; u++) {
        float a = row[t*8+u];
        if (a > 0.f) loc[c++] = t*8+u;
    }
    int lane = t & 31, w = t >> 5;
    int v = c;
    #pragma unroll
    for (int m=1; m<32; m<<=1) {
        int y = __shfl_up_sync(0xffffffffu, v, m);
        if (lane >= m) v += y;
    }
    __shared__ int wtot[8];
    if (lane == 31) wtot[w] = v;
    __syncthreads();
    int woff = 0;
    #pragma unroll
    for (int i=0; i<8; i++) woff += (i < w) ? wtot[i] : 0;
    int base2 = woff + v - c;   // exclusive prefix
    for (int i=0; i<c; i++) {
        int p = base2 + i;
        if (p < NCAP) g_nbr[n*NCAP + p] = loc[i];
    }
    if (t == 255) {
        int tot = woff + v;
        g_cnt[n] = (tot < NCAP) ? tot : NCAP;
    }
}

// ============ 64x256 GEMM for 1024-thread fat blocks (K=256, ldb=256) =======
// tx=tid&31 (col lane), ty=tid>>5 (warp = 2 rows). acc2[2][4].
__device__ void mm64_1024(const float* __restrict__ A,
                          const float* __restrict__ B,
                          float* __restrict__ Dst, float* dyn) {
    float* As = dyn;
    float* Bs = dyn + 3*ASLOT;
    int tid = threadIdx.x;
    int tx = tid & 31, ty = tid >> 5;
    unsigned long long acc2[2][4];
    #pragma unroll
    for (int r=0;r<2;r++)
        #pragma unroll
        for (int p=0;p<4;p++) acc2[r][p] = 0ull;

    const int T = 16;  // K=256 / 16
    // load helper inline (slot, k0)
    #define FAT_LOAD(slot, k0) do { \
        if (tid < 256) { int r_ = tid >> 2, c_ = (tid & 3) * 4; \
            cp16(As + (slot)*ASLOT + r_*LDA_S + c_, A + (size_t)r_*Dd + (k0) + c_); } \
        { int kk_ = tid >> 6, c_ = (tid & 63) * 4; \
            cp16(Bs + (slot)*BSLOT + kk_*LDB_S + c_, B + (size_t)((k0)+kk_)*Dd + c_); } \
    } while(0)

    FAT_LOAD(0, 0);
    cp_commit();
    FAT_LOAD(1, 16);
    cp_commit();

    for (int t = 0; t < T; t++) {
        cp_wait<1>();
        __syncthreads();
        if (t+2 < T) {
            int slot = (t+2) % 3;
            FAT_LOAD(slot, (t+2)*16);
            cp_commit();
        } else {
            cp_commit();
        }
        int cur = t % 3;
        const float* Asc = As + cur*ASLOT;
        const float* Bsc = Bs + cur*BSLOT;
        #pragma unroll
        for (int k4 = 0; k4 < 4; k4++) {
            float4 a[2];
            #pragma unroll
            for (int r=0;r<2;r++)
                a[r] = *(const float4*)(Asc + (2*ty+r)*LDA_S + k4*4);
            #pragma unroll
            for (int u=0;u<4;u++) {
                const float* brow = Bsc + (k4*4+u)*LDB_S;
                ulonglong2 b0 = *(const ulonglong2*)(brow + tx*4);
                ulonglong2 b1 = *(const ulonglong2*)(brow + 128 + tx*4);
                #pragma unroll
                for (int r=0;r<2;r++) {
                    float av = (u==0) ? a[r].x : (u==1) ? a[r].y : (u==2) ? a[r].z : a[r].w;
                    unsigned long long a2 = dup2(av);
                    fma2(acc2[r][0], a2, b0.x);
                    fma2(acc2[r][1], a2, b0.y);
                    fma2(acc2[r][2], a2, b1.x);
                    fma2(acc2[r][3], a2, b1.y);
                }
            }
        }
    }
    __syncthreads();
    #pragma unroll
    for (int r=0;r<2;r++) {
        float o0,o1,o2,o3,o4,o5,o6,o7;
        unpack2(acc2[r][0], o0, o1);
        unpack2(acc2[r][1], o2, o3);
        unpack2(acc2[r][2], o4, o5);
        unpack2(acc2[r][3], o6, o7);
        float* drow = Dst + (size_t)(2*ty+r)*Dd;
        *(float4*)(drow + tx*4)       = make_float4(o0,o1,o2,o3);
        *(float4*)(drow + 128 + tx*4) = make_float4(o4,o5,o6,o7);
    }
    #undef FAT_LOAD
}

// ===================== FAT kernel: block 0 = Lanczos, blocks 1..128 = y+GEMMs
__global__ void __launch_bounds__(1024) k_fat(const float* __restrict__ L,
                                              const float* __restrict__ x,
                                              const float* __restrict__ Wc) {
    extern __shared__ float dyn[];
    if (blockIdx.x != 0) {
        // ---------------- y = deg*x - sum_nbr x  for 64 rows, then 2 GEMMs ---
        int bid = blockIdx.x - 1;      // 0..127
        int rbase = bid * 64;
        int tid = threadIdx.x;
        {
            int cg = (tid & 63) * 4;
            int rr0 = tid >> 6;        // 0..15
            #pragma unroll
            for (int k = 0; k < 4; k++) {
                int row = rbase + rr0 + k*16;
                int b = row >> 11, n = row & 2047;
                float deg = L[(size_t)n*Nn + n];
                int cnt = g_cnt[n];
                const int* nb = g_nbr + n*NCAP;
                const float* xb = x + (size_t)b*Nn*Dd;
                float ax=0.f, ay=0.f, az=0.f, aw=0.f;
                for (int i=0;i<cnt;i++){
                    int j = nb[i];
                    if (j != n) {
                        float4 xv = *(const float4*)(xb + (size_t)j*Dd + cg);
                        ax+=xv.x; ay+=xv.y; az+=xv.z; aw+=xv.w;
                    }
                }
                float4 xv = *(const float4*)(xb + (size_t)n*Dd + cg);
                *(float4*)(g_xp + (size_t)row*Dd + cg) =
                    make_float4(deg*xv.x-ax, deg*xv.y-ay, deg*xv.z-az, deg*xv.w-aw);
            }
        }
        __syncthreads();   // y visible block-wide
        mm64_1024(g_xp + (size_t)rbase*Dd, Wc, g_gy + (size_t)rbase*Dd, dyn);
        __syncthreads();   // smem reuse safe
        mm64_1024(x    + (size_t)rbase*Dd, Wc, g_gx + (size_t)rbase*Dd, dyn);
        return;
    }

    // ---------------- block 0: Lanczos (R15-proven code, verbatim) ----------
    float* vc  = dyn;                 // 2048
    float* vp  = vc + 2048;           // 2048
    float* red = vp + 2048;           // 128
    int*   snbr = (int*)(red + 128);  // CAP_E entries
    __shared__ float s_alpha[LZM], s_beta[LZM];
    __shared__ int iws[32];

    int t = threadIdx.x;
    int lane = t & 31, wid = t >> 5;
    int r0 = t, r1 = t + 1024;
    float deg0 = L[(size_t)r0*Nn + r0];
    float deg1 = L[(size_t)r1*Nn + r1];
    int cnt0 = g_cnt[r0], cnt1 = g_cnt[r1];
    int c0 = cnt0 - 1, c1 = cnt1 - 1;
    const int* nb0 = g_nbr + r0*NCAP;
    const int* nb1 = g_nbr + r1*NCAP;

    int incl = c0;
    #pragma unroll
    for (int m=1; m<32; m<<=1) { int y=__shfl_up_sync(0xffffffffu,incl,m); if (lane>=m) incl+=y; }
    if (lane == 31) iws[wid] = incl;
    __syncthreads();
    if (wid == 0) {
        int v = iws[lane];
        #pragma unroll
        for (int m=1; m<32; m<<=1) { int y=__shfl_up_sync(0xffffffffu,v,m); if (lane>=m) v+=y; }
        iws[lane] = v;
    }
    __syncthreads();
    int start0 = (wid>0 ? iws[wid-1] : 0) + incl - c0;
    int total0 = iws[31];
    __syncthreads();
    incl = c1;
    #pragma unroll
    for (int m=1; m<32; m<<=1) { int y=__shfl_up_sync(0xffffffffu,incl,m); if (lane>=m) incl+=y; }
    if (lane == 31) iws[wid] = incl;
    __syncthreads();
    if (wid == 0) {
        int v = iws[lane];
        #pragma unroll
        for (int m=1; m<32; m<<=1) { int y=__shfl_up_sync(0xffffffffu,v,m); if (lane>=m) v+=y; }
        iws[lane] = v;
    }
    __syncthreads();
    int start1 = total0 + (wid>0 ? iws[wid-1] : 0) + incl - c1;

    bool fb0 = (start0 + c0 > CAP_E);
    bool fb1 = (start1 + c1 > CAP_E);
    if (!fb0) { int k=0; for (int i=0;i<cnt0;i++){ int jn=nb0[i]; if (jn!=r0) snbr[start0+k++]=jn; } }
    if (!fb1) { int k=0; for (int i=0;i<cnt1;i++){ int jn=nb1[i]; if (jn!=r1) snbr[start1+k++]=jn; } }

    float a0 = sinf(0.7318f*(float)r0 + 0.2f) + 0.001f;
    float a1 = sinf(0.7318f*(float)r1 + 0.2f) + 0.001f;
    {
        float pn = a0*a0 + a1*a1;
        #pragma unroll
        for (int m=16;m>0;m>>=1) pn += __shfl_xor_sync(0xffffffffu, pn, m);
        if (lane==0) red[wid] = pn;
        __syncthreads();
        if (t < 32) {
            float xx = red[t];
            #pragma unroll
            for (int m=16;m>0;m>>=1) xx += __shfl_xor_sync(0xffffffffu, xx, m);
            if (t==0) red[32] = xx;
        }
        __syncthreads();
    }
    float inv0 = rsqrtf(red[32]);
    vc[r0] = a0*inv0; vc[r1] = a1*inv0;
    vp[r0] = 0.f;     vp[r1] = 0.f;
    float beta_prev = 0.f;
    __syncthreads();

    for (int j = 0; j < LZM; j++) {
        float s0 = 0.f, s1 = 0.f;
        if (!fb0) {
            #pragma unroll 4
            for (int i=start0; i<start0+c0; i++) s0 += vc[snbr[i]];
        } else {
            #pragma unroll 4
            for (int i=0; i<cnt0; i++){ int jn=nb0[i]; if (jn!=r0) s0 += vc[jn]; }
        }
        if (!fb1) {
            #pragma unroll 4
            for (int i=start1; i<start1+c1; i++) s1 += vc[snbr[i]];
        } else {
            #pragma unroll 4
            for (int i=0; i<cnt1; i++){ int jn=nb1[i]; if (jn!=r1) s1 += vc[jn]; }
        }
        float w0 = deg0*vc[r0] - s0 - beta_prev*vp[r0];
        float w1 = deg1*vc[r1] - s1 - beta_prev*vp[r1];
        float pa = w0*vc[r0] + w1*vc[r1];
        #pragma unroll
        for (int m=16;m>0;m>>=1) pa += __shfl_xor_sync(0xffffffffu, pa, m);
        if (lane==0) red[wid] = pa;
        __syncthreads();
        if (t < 32) {
            float xx = red[t];
            #pragma unroll
            for (int m=16;m>0;m>>=1) xx += __shfl_xor_sync(0xffffffffu, xx, m);
            if (t==0) red[32] = xx;
        }
        __syncthreads();
        float alpha = red[32];
        w0 -= alpha*vc[r0]; w1 -= alpha*vc[r1];
        float pb = w0*w0 + w1*w1;
        #pragma unroll
        for (int m=16;m>0;m>>=1) pb += __shfl_xor_sync(0xffffffffu, pb, m);
        if (lane==0) red[wid] = pb;
        __syncthreads();
        if (t < 32) {
            float xx = red[t];
            #pragma unroll
            for (int m=16;m>0;m>>=1) xx += __shfl_xor_sync(0xffffffffu, xx, m);
            if (t==0) red[33] = xx;
        }
        __syncthreads();
        float tot = red[33];
        float beta_j = sqrtf(tot);
        float invb = rsqrtf(tot + 1e-30f);
        vp[r0] = vc[r0]; vp[r1] = vc[r1];
        vc[r0] = w0*invb; vc[r1] = w1*invb;
        if (t == 0) { s_alpha[j] = alpha; s_beta[j] = beta_j; }
        beta_prev = beta_j;
        __syncthreads();
    }

    if (t < 32) {
        float lo = s_alpha[0], hi = s_alpha[0];
        float sb2[LZM];
        for (int i=0;i<LZM;i++) {
            float r = (i>0?fabsf(s_beta[i-1]):0.f) + (i<LZM-1?fabsf(s_beta[i]):0.f);
            lo = fminf(lo, s_alpha[i]-r);
            hi = fmaxf(hi, s_alpha[i]+r);
            sb2[i] = (i>0) ? s_beta[i-1]*s_beta[i-1] : 0.f;
        }
        lo -= 1.f; hi += 1.f;
        for (int round=0; round<8; round++) {
            float w  = (hi-lo)*(1.0f/33.0f);
            float xp = lo + w*(float)(t+1);
            int cnt = 0;
            float d = s_alpha[0]-xp; if (d<0.f) cnt++;
            #pragma unroll 4
            for (int i=1;i<LZM;i++){
                if (d==0.f) d = -1e-30f;
                d = s_alpha[i]-xp - __fdividef(sb2[i], d);
                if (d<0.f) cnt++;
            }
            unsigned m = __ballot_sync(0xffffffffu, cnt >= LZM);
            if (m == 0u) {
                lo = lo + w*32.f;
            } else {
                int f = __ffs(m)-1;
                hi = lo + w*(float)(f+1);
                lo = lo + w*(float)f;
            }
        }
        if (t==0) {
            float lam = 0.5f*(lo+hi) + 1e-8f;
            g_scale2 = 2.0f/lam;
        }
    }
}
#define LZ_SMEM ((2048+2048+128)*4 + CAP_E*4)

// ===== x1 epilogue: x1 = relu(LN(s2*Gy - Gx + bc)) + x  (warp per row) ======
__device__ __forceinline__ void ln_row_w(float v[8], const float* __restrict__ g,
                                         const float* __restrict__ be, int tx, bool do_relu) {
    float s = 0.f;
    #pragma unroll
    for (int u=0;u<8;u++) s += v[u];
    #pragma unroll
    for (int m=1;m<32;m<<=1) s += __shfl_xor_sync(0xffffffffu, s, m);
    float mu = s * (1.0f/256.0f);
    float q = 0.f;
    #pragma unroll
    for (int u=0;u<8;u++){ float d = v[u]-mu; q += d*d; }
    #pragma unroll
    for (int m=1;m<32;m<<=1) q += __shfl_xor_sync(0xffffffffu, q, m);
    float inv = rsqrtf(q*(1.0f/256.0f) + 1e-5f);
    #pragma unroll
    for (int u=0;u<8;u++){
        int col = (u<4) ? (tx*4+u) : (128 + tx*4 + (u-4));
        float t = (v[u]-mu)*inv*g[col] + be[col];
        if (do_relu) t = fmaxf(t, 0.f);
        v[u] = t;
    }
}

__global__ void __launch_bounds__(256) k_x1_post(const float* __restrict__ x,
                                                 const float* __restrict__ bc,
                                                 const float* __restrict__ g1,
                                                 const float* __restrict__ be1) {
    int row = blockIdx.x*8 + (threadIdx.x >> 5);
    int lane = threadIdx.x & 31;
    float s2 = g_scale2;
    const float* gy = g_gy + (size_t)row*Dd;
    const float* gx = g_gx + (size_t)row*Dd;
    float4 y0 = *(const float4*)(gy + lane*4);
    float4 y1 = *(const float4*)(gy + 128 + lane*4);
    float4 x0 = *(const float4*)(gx + lane*4);
    float4 x1 = *(const float4*)(gx + 128 + lane*4);
    int c0 = lane*4, c1 = 128 + lane*4;
    float v[8];
    v[0] = s2*y0.x - x0.x + bc[c0+0];
    v[1] = s2*y0.y - x0.y + bc[c0+1];
    v[2] = s2*y0.z - x0.z + bc[c0+2];
    v[3] = s2*y0.w - x0.w + bc[c0+3];
    v[4] = s2*y1.x - x1.x + bc[c1+0];
    v[5] = s2*y1.y - x1.y + bc[c1+1];
    v[6] = s2*y1.z - x1.z + bc[c1+2];
    v[7] = s2*y1.w - x1.w + bc[c1+3];
    ln_row_w(v, g1, be1, lane, true);
    const float* xr = x + (size_t)row*Dd;
    float4 xv0 = *(const float4*)(xr + lane*4);
    float4 xv1 = *(const float4*)(xr + 128 + lane*4);
    v[0]+=xv0.x; v[1]+=xv0.y; v[2]+=xv0.z; v[3]+=xv0.w;
    v[4]+=xv1.x; v[5]+=xv1.y; v[6]+=xv1.z; v[7]+=xv1.w;
    float* dst = g_x1 + (size_t)row*Dd;
    *(float4*)(dst + lane*4)       = make_float4(v[0], v[1], v[2], v[3]);
    *(float4*)(dst + 128 + lane*4) = make_float4(v[4], v[5], v[6], v[7]);
}

// ===================== sparse attention (exact) ==============================
__global__ void __launch_bounds__(256) k_attn_sp() {
    int wid = threadIdx.x >> 5, lane = threadIdx.x & 31;
    int gw = blockIdx.x*8 + wid;           // 0..16383
    int bh = gw >> 11;
    int n  = gw & 2047;
    int b = bh >> 2, h = bh & 3;

    const float* qg = g_q + ((size_t)bh*Nn + n)*HD;
    float2 q2 = *(const float2*)(qg + lane*2);

    int cnt = g_cnt[n];
    const int* nb = g_nbr + n*NCAP;

    int id[3] = {0,0,0};
    #pragma unroll
    for (int k=0;k<3;k++) { int j = lane + 32*k; if (j < cnt) id[k] = nb[j]; }

    const float* kg = g_kk + (size_t)bh*Nn*HD;
    float s[3] = {-1e30f,-1e30f,-1e30f};
    for (int j=0; j<cnt; j++) {
        int idx = __shfl_sync(0xffffffffu, id[j>>5], j&31);
        float2 k2 = *(const float2*)(kg + (size_t)idx*HD + lane*2);
        float d = q2.x*k2.x + q2.y*k2.y;
        #pragma unroll
        for (int m=16;m>0;m>>=1) d += __shfl_xor_sync(0xffffffffu, d, m);
        if (lane == (j&31) && (j>>5) == 0) s[0] = d*0.125f;
        if (lane == (j&31) && (j>>5) == 1) s[1] = d*0.125f;
        if (lane == (j&31) && (j>>5) == 2) s[2] = d*0.125f;
    }
    float mx = fmaxf(s[0], fmaxf(s[1], s[2]));
    #pragma unroll
    for (int m=16;m>0;m>>=1) mx = fmaxf(mx, __shfl_xor_sync(0xffffffffu, mx, m));
    float p[3];
    float l = 0.f;
    #pragma unroll
    for (int k=0;k<3;k++){ p[k] = __expf(s[k]-mx); l += p[k]; }
    #pragma unroll
    for (int m=16;m>0;m>>=1) l += __shfl_xor_sync(0xffffffffu, l, m);

    const float* vg = g_v + (size_t)bh*Nn*HD;
    float ox = 0.f, oy = 0.f;
    for (int j=0; j<cnt; j++) {
        float pj = __shfl_sync(0xffffffffu, p[j>>5], j&31);
        int  idx = __shfl_sync(0xffffffffu, id[j>>5], j&31);
        float2 v2 = *(const float2*)(vg + (size_t)idx*HD + lane*2);
        ox += pj*v2.x; oy += pj*v2.y;
    }
    float invl = 1.0f / l;
    float2 o2 = make_float2(ox*invl, oy*invl);
    *(float2*)(g_o + ((size_t)(b*Nn) + n)*Dd + h*HD + lane*2) = o2;
}

// ===================== 64x256 GEMM (3-stage cp.async, 1 bar/stage, FFMA2) ===
// 256 threads: tx=tid&31 (col lane), ty=tid>>5 (warp = 8 rows).
__device__ __forceinline__ void load_tiles64(const float* __restrict__ A, int lda,
                                             const float* __restrict__ B, int ldb,
                                             int k0, float* As, float* Bs, int tid) {
    { // A tile 64x16: one cp16 per thread
        int r = tid >> 2, c = (tid & 3) * 4;
        cp16(As + r*LDA_S + c, A + (size_t)r*lda + k0 + c);
    }
    #pragma unroll
    for (int u=0; u<4; u++) { // B tile 16x256
        int o = tid*4 + u;                 // 0..1023
        int kk = o >> 6, c = (o & 63) * 4;
        cp16(Bs + kk*LDB_S + c, B + (size_t)(k0+kk)*ldb + c);
    }
}

__device__ __forceinline__ void mm64x256(const float* __restrict__ A, int lda,
                                         const float* __restrict__ B, int ldb,
                                         int K, float acc[8][8],
                                         float* As, float* Bs) {
    int tid = threadIdx.x;
    int tx = tid & 31, ty = tid >> 5;
    unsigned long long acc2[8][4];
    #pragma unroll
    for (int r=0;r<8;r++)
        #pragma unroll
        for (int p=0;p<4;p++) acc2[r][p] = 0ull;

    int T = K / 16;
    load_tiles64(A, lda, B, ldb, 0,  As,          Bs,          tid);
    cp_commit();
    load_tiles64(A, lda, B, ldb, 16, As + ASLOT,  Bs + BSLOT,  tid);
    cp_commit();

    for (int t = 0; t < T; t++) {
        cp_wait<1>();
        __syncthreads();
        if (t+2 < T) {
            int slot = (t+2) % 3;
            load_tiles64(A, lda, B, ldb, (t+2)*16,
                         As + slot*ASLOT, Bs + slot*BSLOT, tid);
            cp_commit();
        } else {
            cp_commit();
        }
        int cur = t % 3;
        const float* Asc = As + cur*ASLOT;
        const float* Bsc = Bs + cur*BSLOT;
        #pragma unroll
        for (int k4 = 0; k4 < 4; k4++) {
            float4 a[8];
            #pragma unroll
            for (int r=0;r<8;r++)
                a[r] = *(const float4*)(Asc + (8*ty+r)*LDA_S + k4*4);
            #pragma unroll
            for (int u=0;u<4;u++) {
                const float* brow = Bsc + (k4*4+u)*LDB_S;
                ulonglong2 b0 = *(const ulonglong2*)(brow + tx*4);
                ulonglong2 b1 = *(const ulonglong2*)(brow + 128 + tx*4);
                #pragma unroll
                for (int r=0;r<8;r++) {
                    float av = (u==0) ? a[r].x : (u==1) ? a[r].y : (u==2) ? a[r].z : a[r].w;
                    unsigned long long a2 = dup2(av);
                    fma2(acc2[r][0], a2, b0.x);
                    fma2(acc2[r][1], a2, b0.y);
                    fma2(acc2[r][2], a2, b1.x);
                    fma2(acc2[r][3], a2, b1.y);
                }
            }
        }
    }
    __syncthreads();
    #pragma unroll
    for (int r=0;r<8;r++)
        #pragma unroll
        for (int p=0;p<4;p++)
            unpack2(acc2[r][p], acc[r][2*p], acc[r][2*p+1]);
}

__device__ __forceinline__ void store_row8(float* dst, const float v[8], int tx) {
    *(float4*)(dst + tx*4)       = make_float4(v[0], v[1], v[2], v[3]);
    *(float4*)(dst + 128 + tx*4) = make_float4(v[4], v[5], v[6], v[7]);
}

#define GEMM_SMEM_DECL __shared__ float As[3*64*LDA_S]; __shared__ float Bs[3*16*LDB_S]

// ---- qkv = x1 @ W, stored (b,h,n,d) ----------------------------------------
__global__ void __launch_bounds__(256) k_gemm_qkv(const float* __restrict__ Wq,
                                                  const float* __restrict__ Wk,
                                                  const float* __restrict__ Wv) {
    GEMM_SMEM_DECL;
    float acc[8][8];
    const float* W = (blockIdx.y==0) ? Wq : (blockIdx.y==1) ? Wk : Wv;
    float* dst0 = (blockIdx.y==0) ? g_q : (blockIdx.y==1) ? g_kk : g_v;
    const float* A = g_x1 + (size_t)blockIdx.x*64*Dd;
    mm64x256(A, Dd, W, Dd, Dd, acc, As, Bs);
    int tx = threadIdx.x & 31, ty = threadIdx.x >> 5;
    int h0 = tx >> 4;
    int co = (tx*4) & 63;
    #pragma unroll
    for (int rr=0; rr<8; rr++) {
        int row = blockIdx.x*64 + 8*ty + rr;
        int b = row >> 11, n = row & 2047;
        *(float4*)(dst0 + ((size_t)(b*4 + h0    )*Nn + n)*HD + co) =
            make_float4(acc[rr][0], acc[rr][1], acc[rr][2], acc[rr][3]);
        *(float4*)(dst0 + ((size_t)(b*4 + 2 + h0)*Nn + n)*HD + co) =
            make_float4(acc[rr][4], acc[rr][5], acc[rr][6], acc[rr][7]);
    }
}

// ---- x2 = LN(x1 + o@Wo + bo) ------------------------------------------------
__global__ void __launch_bounds__(256) k_gemm_x2(const float* __restrict__ Wo,
                                                 const float* __restrict__ bo,
                                                 const float* __restrict__ g2,
                                                 const float* __restrict__ be2) {
    GEMM_SMEM_DECL;
    float acc[8][8];
    const float* A = g_o + (size_t)blockIdx.x*64*Dd;
    mm64x256(A, Dd, Wo, Dd, Dd, acc, As, Bs);
    int tx = threadIdx.x & 31, ty = threadIdx.x >> 5;
    #pragma unroll
    for (int rr=0; rr<8; rr++) {
        int row = blockIdx.x*64 + 8*ty + rr;
        const float* x1r = g_x1 + (size_t)row*Dd;
        float4 xv0 = *(const float4*)(x1r + tx*4);
        float4 xv1 = *(const float4*)(x1r + 128 + tx*4);
        int c0 = tx*4, c1 = 128 + tx*4;
        float v[8];
        v[0] = acc[rr][0] + bo[c0+0] + xv0.x;
        v[1] = acc[rr][1] + bo[c0+1] + xv0.y;
        v[2] = acc[rr][2] + bo[c0+2] + xv0.z;
        v[3] = acc[rr][3] + bo[c0+3] + xv0.w;
        v[4] = acc[rr][4] + bo[c1+0] + xv1.x;
        v[5] = acc[rr][5] + bo[c1+1] + xv1.y;
        v[6] = acc[rr][6] + bo[c1+2] + xv1.z;
        v[7] = acc[rr][7] + bo[c1+3] + xv1.w;
        ln_row_w(v, g2, be2, tx, false);
        store_row8(g_x2 + (size_t)row*Dd, v, tx);
    }
}

// ---- mt = gelu(x2@W1 + b1)  (N=512 via 2 col blocks) ------------------------
__global__ void __launch_bounds__(256) k_gemm_m1(const float* __restrict__ W1,
                                                 const float* __restrict__ b1) {
    GEMM_SMEM_DECL;
    float acc[8][8];
    int cb = blockIdx.y;
    const float* A = g_x2 + (size_t)blockIdx.x*64*Dd;
    mm64x256(A, Dd, W1 + cb*256, HID, Dd, acc, As, Bs);
    int tx = threadIdx.x & 31, ty = threadIdx.x >> 5;
    #pragma unroll
    for (int rr=0; rr<8; rr++) {
        int row = blockIdx.x*64 + 8*ty + rr;
        float v[8];
        #pragma unroll
        for (int u=0;u<8;u++){
            int col = (u<4) ? (tx*4+u) : (128 + tx*4 + (u-4));
            float t = acc[rr][u] + b1[cb*256 + col];
            v[u] = 0.5f*t*(1.0f + erff(t*0.70710678118654752f));
        }
        store_row8(g_mt + (size_t)row*HID + cb*256, v, tx);
    }
}

// ---- out = LN(x2 + mt@W2 + b2) ----------------------------------------------
__global__ void __launch_bounds__(256) k_gemm_out(const float* __restrict__ W2,
                                                  const float* __restrict__ b2,
                                                  const float* __restrict__ g3,
                                                  const float* __restrict__ be3,
                                                  float* __restrict__ out) {
    GEMM_SMEM_DECL;
    float acc[8][8];
    const float* A = g_mt + (size_t)blockIdx.x*64*HID;
    mm64x256(A, HID, W2, Dd, HID, acc, As, Bs);
    int tx = threadIdx.x & 31, ty = threadIdx.x >> 5;
    #pragma unroll
    for (int rr=0; rr<8; rr++) {
        int row = blockIdx.x*64 + 8*ty + rr;
        const float* x2r = g_x2 + (size_t)row*Dd;
        float4 xv0 = *(const float4*)(x2r + tx*4);
        float4 xv1 = *(const float4*)(x2r + 128 + tx*4);
        int c0 = tx*4, c1 = 128 + tx*4;
        float v[8];
        v[0] = acc[rr][0] + b2[c0+0] + xv0.x;
        v[1] = acc[rr][1] + b2[c0+1] + xv0.y;
        v[2] = acc[rr][2] + b2[c0+2] + xv0.z;
        v[3] = acc[rr][3] + b2[c0+3] + xv0.w;
        v[4] = acc[rr][4] + b2[c1+0] + xv1.x;
        v[5] = acc[rr][5] + b2[c1+1] + xv1.y;
        v[6] = acc[rr][6] + b2[c1+2] + xv1.z;
        v[7] = acc[rr][7] + b2[c1+3] + xv1.w;
        ln_row_w(v, g3, be3, tx, false);
        store_row8(out + (size_t)row*Dd, v, tx);
    }
}

// ============================ launch =========================================
extern "C" void kernel_launch(void* const* d_in, const int* in_sizes, int n_in,
                              void* d_out, int out_size) {
    const float* x   = (const float*)d_in[0];
    const float* L   = (const float*)d_in[1];
    const float* adj = (const float*)d_in[2];
    const float* Wc  = (const float*)d_in[3];
    const float* bc  = (const float*)d_in[4];
    const float* g1  = (const float*)d_in[5];
    const float* be1 = (const float*)d_in[6];
    const float* Wq  = (const float*)d_in[7];
    const float* Wk  = (const float*)d_in[8];
    const float* Wv  = (const float*)d_in[9];
    const float* Wo  = (const float*)d_in[10];
    const float* bo  = (const float*)d_in[11];
    const float* g2  = (const float*)d_in[12];
    const float* be2 = (const float*)d_in[13];
    const float* W1  = (const float*)d_in[14];
    const float* b1  = (const float*)d_in[15];
    const float* W2  = (const float*)d_in[16];
    const float* b2  = (const float*)d_in[17];
    const float* g3  = (const float*)d_in[18];
    const float* be3 = (const float*)d_in[19];
    float* out = (float*)d_out;

    cudaFuncSetAttribute(k_fat, cudaFuncAttributeMaxDynamicSharedMemorySize, LZ_SMEM);

    k_build_nbr<<<Nn, 256>>>(adj);                          // 1
    k_fat      <<<1 + Mrows/64, 1024, LZ_SMEM>>>(L, x, Wc); // 2: lz || y+Gy+Gx
    k_x1_post  <<<Mrows/8, 256>>>(x, bc, g1, be1);          // 3
    k_gemm_qkv <<<dim3(Mrows/64, 3), 256>>>(Wq, Wk, Wv);    // 4  <-- ncu
    k_attn_sp  <<<Bz*4*Nn/8, 256>>>();                      // 5
    k_gemm_x2  <<<Mrows/64, 256>>>(Wo, bo, g2, be2);        // 6
    k_gemm_m1  <<<dim3(Mrows/64, 2), 256>>>(W1, b1);        // 7
    k_gemm_out <<<Mrows/64, 256>>>(W2, b2, g3, be3, out);   // 8
}

// round 17
// speedup vs baseline: 1.3335x; 1.1055x over previous
#include <cuda_runtime.h>
#include <math.h>
#include <stdint.h>

// Problem dims
#define Bz   4
#define Nn   2048
#define Dd   256
#define HD   64
#define HID  512
#define Mrows (Bz*Nn)          // 8192
#define LZM  24                // Lanczos iterations (numerics path identical to proven 32)
#define NCAP 80                // neighbor cap (max degree ~35 incl self)
#define CAP_E 45056            // smem CSR capacity (expected nnz ~34k)

// ---------------- device scratch (static; no allocations allowed) ----------
__device__ float g_scale2;     // 2 / lam_max

__device__ float g_xp[Mrows*Dd];   // holds y = deg*x - sum_nbr x
__device__ float g_gy[Mrows*Dd];   // y @ Wc
__device__ float g_gx[Mrows*Dd];   // x @ Wc
__device__ float g_x1[Mrows*Dd];
__device__ float g_q [Bz*4*Nn*HD];
__device__ float g_kk[Bz*4*Nn*HD];
__device__ float g_v [Bz*4*Nn*HD];
__device__ float g_o [Mrows*Dd];
__device__ float g_x2[Mrows*Dd];
__device__ float g_mt[Mrows*HID];
__device__ int   g_nbr[Nn*NCAP];
__device__ int   g_cnt[Nn];

// ---------------- cp.async helpers -----------------------------------------
__device__ __forceinline__ void cp16(float* dst, const float* src) {
    uint32_t d = (uint32_t)__cvta_generic_to_shared(dst);
    asm volatile("cp.async.cg.shared.global [%0], [%1], 16;\n" :: "r"(d), "l"(src));
}
__device__ __forceinline__ void cp_commit() { asm volatile("cp.async.commit_group;\n"); }
template<int N>
__device__ __forceinline__ void cp_wait() { asm volatile("cp.async.wait_group %0;\n" :: "n"(N)); }

// ---------------- packed f32x2 FMA (SASS FFMA2 — full fp32-core rate) -------
__device__ __forceinline__ void fma2(unsigned long long& d, unsigned long long a,
                                     unsigned long long b) {
    asm("fma.rn.f32x2 %0, %1, %2, %0;" : "+l"(d) : "l"(a), "l"(b));
}
__device__ __forceinline__ unsigned long long dup2(float v) {
    unsigned long long r;
    uint32_t u = __float_as_uint(v);
    asm("mov.b64 %0, {%1, %1};" : "=l"(r) : "r"(u));
    return r;
}
__device__ __forceinline__ void unpack2(unsigned long long p, float& lo, float& hi) {
    uint32_t l, h;
    asm("mov.b64 {%0, %1}, %2;" : "=r"(l), "=r"(h) : "l"(p));
    lo = __uint_as_float(l); hi = __uint_as_float(h);
}

#define LDA_S 20
#define LDB_S 260
#define ASLOT (64*LDA_S)
#define BSLOT (16*LDB_S)

// ===================== neighbor list build (ordered compaction) =============
__global__ void __launch_bounds__(256) k_build_nbr(const float* __restrict__ adj) {
    int n = blockIdx.x;
    int t = threadIdx.x;
    const float* row = adj + (size_t)n*Nn;
    int loc[8]; int c = 0;
    #pragma unroll
    for (int u=0; u<8; u++) {
        float a = row[t*8+u];
        if (a > 0.f) loc[c++] = t*8+u;
    }
    int lane = t & 31, w = t >> 5;
    int v = c;
    #pragma unroll
    for (int m=1; m<32; m<<=1) {
        int y = __shfl_up_sync(0xffffffffu, v, m);
        if (lane >= m) v += y;
    }
    __shared__ int wtot[8];
    if (lane == 31) wtot[w] = v;
    __syncthreads();
    int woff = 0;
    #pragma unroll
    for (int i=0; i<8; i++) woff += (i < w) ? wtot[i] : 0;
    int base2 = woff + v - c;   // exclusive prefix
    for (int i=0; i<c; i++) {
        int p = base2 + i;
        if (p < NCAP) g_nbr[n*NCAP + p] = loc[i];
    }
    if (t == 255) {
        int tot = woff + v;
        g_cnt[n] = (tot < NCAP) ? tot : NCAP;
    }
}

// ============ 64x256 GEMM for 1024-thread fat blocks (K=256, ldb=256) =======
__device__ void mm64_1024(const float* __restrict__ A,
                          const float* __restrict__ B,
                          float* __restrict__ Dst, float* dyn) {
    float* As = dyn;
    float* Bs = dyn + 3*ASLOT;
    int tid = threadIdx.x;
    int tx = tid & 31, ty = tid >> 5;
    unsigned long long acc2[2][4];
    #pragma unroll
    for (int r=0;r<2;r++)
        #pragma unroll
        for (int p=0;p<4;p++) acc2[r][p] = 0ull;

    const int T = 16;  // K=256 / 16
    #define FAT_LOAD(slot, k0) do { \
        if (tid < 256) { int r_ = tid >> 2, c_ = (tid & 3) * 4; \
            cp16(As + (slot)*ASLOT + r_*LDA_S + c_, A + (size_t)r_*Dd + (k0) + c_); } \
        { int kk_ = tid >> 6, c_ = (tid & 63) * 4; \
            cp16(Bs + (slot)*BSLOT + kk_*LDB_S + c_, B + (size_t)((k0)+kk_)*Dd + c_); } \
    } while(0)

    FAT_LOAD(0, 0);
    cp_commit();
    FAT_LOAD(1, 16);
    cp_commit();

    for (int t = 0; t < T; t++) {
        cp_wait<1>();
        __syncthreads();
        if (t+2 < T) {
            int slot = (t+2) % 3;
            FAT_LOAD(slot, (t+2)*16);
            cp_commit();
        } else {
            cp_commit();
        }
        int cur = t % 3;
        const float* Asc = As + cur*ASLOT;
        const float* Bsc = Bs + cur*BSLOT;
        #pragma unroll
        for (int k4 = 0; k4 < 4; k4++) {
            float4 a[2];
            #pragma unroll
            for (int r=0;r<2;r++)
                a[r] = *(const float4*)(Asc + (2*ty+r)*LDA_S + k4*4);
            #pragma unroll
            for (int u=0;u<4;u++) {
                const float* brow = Bsc + (k4*4+u)*LDB_S;
                ulonglong2 b0 = *(const ulonglong2*)(brow + tx*4);
                ulonglong2 b1 = *(const ulonglong2*)(brow + 128 + tx*4);
                #pragma unroll
                for (int r=0;r<2;r++) {
                    float av = (u==0) ? a[r].x : (u==1) ? a[r].y : (u==2) ? a[r].z : a[r].w;
                    unsigned long long a2 = dup2(av);
                    fma2(acc2[r][0], a2, b0.x);
                    fma2(acc2[r][1], a2, b0.y);
                    fma2(acc2[r][2], a2, b1.x);
                    fma2(acc2[r][3], a2, b1.y);
                }
            }
        }
    }
    __syncthreads();
    #pragma unroll
    for (int r=0;r<2;r++) {
        float o0,o1,o2,o3,o4,o5,o6,o7;
        unpack2(acc2[r][0], o0, o1);
        unpack2(acc2[r][1], o2, o3);
        unpack2(acc2[r][2], o4, o5);
        unpack2(acc2[r][3], o6, o7);
        float* drow = Dst + (size_t)(2*ty+r)*Dd;
        *(float4*)(drow + tx*4)       = make_float4(o0,o1,o2,o3);
        *(float4*)(drow + 128 + tx*4) = make_float4(o4,o5,o6,o7);
    }
    #undef FAT_LOAD
}

// ===================== FAT kernel: block 0 = Lanczos, blocks 1..128 = y+GEMMs
__global__ void __launch_bounds__(1024) k_fat(const float* __restrict__ L,
                                              const float* __restrict__ x,
                                              const float* __restrict__ Wc) {
    extern __shared__ float dyn[];
    if (blockIdx.x != 0) {
        int bid = blockIdx.x - 1;      // 0..127
        int rbase = bid * 64;
        int tid = threadIdx.x;
        {
            int cg = (tid & 63) * 4;
            int rr0 = tid >> 6;        // 0..15
            #pragma unroll
            for (int k = 0; k < 4; k++) {
                int row = rbase + rr0 + k*16;
                int b = row >> 11, n = row & 2047;
                float deg = L[(size_t)n*Nn + n];
                int cnt = g_cnt[n];
                const int* nb = g_nbr + n*NCAP;
                const float* xb = x + (size_t)b*Nn*Dd;
                float ax=0.f, ay=0.f, az=0.f, aw=0.f;
                for (int i=0;i<cnt;i++){
                    int j = nb[i];
                    if (j != n) {
                        float4 xv = *(const float4*)(xb + (size_t)j*Dd + cg);
                        ax+=xv.x; ay+=xv.y; az+=xv.z; aw+=xv.w;
                    }
                }
                float4 xv = *(const float4*)(xb + (size_t)n*Dd + cg);
                *(float4*)(g_xp + (size_t)row*Dd + cg) =
                    make_float4(deg*xv.x-ax, deg*xv.y-ay, deg*xv.z-az, deg*xv.w-aw);
            }
        }
        __syncthreads();
        mm64_1024(g_xp + (size_t)rbase*Dd, Wc, g_gy + (size_t)rbase*Dd, dyn);
        __syncthreads();
        mm64_1024(x    + (size_t)rbase*Dd, Wc, g_gx + (size_t)rbase*Dd, dyn);
        return;
    }

    // ---------------- block 0: Lanczos (proven two-pass numerics) -----------
    float* vc  = dyn;                 // 2048
    float* vp  = vc + 2048;           // 2048
    float* red = vp + 2048;           // 128
    int*   snbr = (int*)(red + 128);  // CAP_E entries
    __shared__ float s_alpha[LZM], s_beta[LZM];
    __shared__ int iws[32];

    int t = threadIdx.x;
    int lane = t & 31, wid = t >> 5;
    int r0 = t, r1 = t + 1024;
    float deg0 = L[(size_t)r0*Nn + r0];
    float deg1 = L[(size_t)r1*Nn + r1];
    int cnt0 = g_cnt[r0], cnt1 = g_cnt[r1];
    int c0 = cnt0 - 1, c1 = cnt1 - 1;
    const int* nb0 = g_nbr + r0*NCAP;
    const int* nb1 = g_nbr + r1*NCAP;

    int incl = c0;
    #pragma unroll
    for (int m=1; m<32; m<<=1) { int y=__shfl_up_sync(0xffffffffu,incl,m); if (lane>=m) incl+=y; }
    if (lane == 31) iws[wid] = incl;
    __syncthreads();
    if (wid == 0) {
        int v = iws[lane];
        #pragma unroll
        for (int m=1; m<32; m<<=1) { int y=__shfl_up_sync(0xffffffffu,v,m); if (lane>=m) v+=y; }
        iws[lane] = v;
    }
    __syncthreads();
    int start0 = (wid>0 ? iws[wid-1] : 0) + incl - c0;
    int total0 = iws[31];
    __syncthreads();
    incl = c1;
    #pragma unroll
    for (int m=1; m<32; m<<=1) { int y=__shfl_up_sync(0xffffffffu,incl,m); if (lane>=m) incl+=y; }
    if (lane == 31) iws[wid] = incl;
    __syncthreads();
    if (wid == 0) {
        int v = iws[lane];
        #pragma unroll
        for (int m=1; m<32; m<<=1) { int y=__shfl_up_sync(0xffffffffu,v,m); if (lane>=m) v+=y; }
        iws[lane] = v;
    }
    __syncthreads();
    int start1 = total0 + (wid>0 ? iws[wid-1] : 0) + incl - c1;

    bool fb0 = (start0 + c0 > CAP_E);
    bool fb1 = (start1 + c1 > CAP_E);
    if (!fb0) { int k=0; for (int i=0;i<cnt0;i++){ int jn=nb0[i]; if (jn!=r0) snbr[start0+k++]=jn; } }
    if (!fb1) { int k=0; for (int i=0;i<cnt1;i++){ int jn=nb1[i]; if (jn!=r1) snbr[start1+k++]=jn; } }

    float a0 = sinf(0.7318f*(float)r0 + 0.2f) + 0.001f;
    float a1 = sinf(0.7318f*(float)r1 + 0.2f) + 0.001f;
    {
        float pn = a0*a0 + a1*a1;
        #pragma unroll
        for (int m=16;m>0;m>>=1) pn += __shfl_xor_sync(0xffffffffu, pn, m);
        if (lane==0) red[wid] = pn;
        __syncthreads();
        if (t < 32) {
            float xx = red[t];
            #pragma unroll
            for (int m=16;m>0;m>>=1) xx += __shfl_xor_sync(0xffffffffu, xx, m);
            if (t==0) red[32] = xx;
        }
        __syncthreads();
    }
    float inv0 = rsqrtf(red[32]);
    vc[r0] = a0*inv0; vc[r1] = a1*inv0;
    vp[r0] = 0.f;     vp[r1] = 0.f;
    float beta_prev = 0.f;
    __syncthreads();

    for (int j = 0; j < LZM; j++) {
        float s0 = 0.f, s1 = 0.f;
        if (!fb0) {
            #pragma unroll 4
            for (int i=start0; i<start0+c0; i++) s0 += vc[snbr[i]];
        } else {
            #pragma unroll 4
            for (int i=0; i<cnt0; i++){ int jn=nb0[i]; if (jn!=r0) s0 += vc[jn]; }
        }
        if (!fb1) {
            #pragma unroll 4
            for (int i=start1; i<start1+c1; i++) s1 += vc[snbr[i]];
        } else {
            #pragma unroll 4
            for (int i=0; i<cnt1; i++){ int jn=nb1[i]; if (jn!=r1) s1 += vc[jn]; }
        }
        float w0 = deg0*vc[r0] - s0 - beta_prev*vp[r0];
        float w1 = deg1*vc[r1] - s1 - beta_prev*vp[r1];
        float pa = w0*vc[r0] + w1*vc[r1];
        #pragma unroll
        for (int m=16;m>0;m>>=1) pa += __shfl_xor_sync(0xffffffffu, pa, m);
        if (lane==0) red[wid] = pa;
        __syncthreads();
        if (t < 32) {
            float xx = red[t];
            #pragma unroll
            for (int m=16;m>0;m>>=1) xx += __shfl_xor_sync(0xffffffffu, xx, m);
            if (t==0) red[32] = xx;
        }
        __syncthreads();
        float alpha = red[32];
        w0 -= alpha*vc[r0]; w1 -= alpha*vc[r1];
        float pb = w0*w0 + w1*w1;
        #pragma unroll
        for (int m=16;m>0;m>>=1) pb += __shfl_xor_sync(0xffffffffu, pb, m);
        if (lane==0) red[wid] = pb;
        __syncthreads();
        if (t < 32) {
            float xx = red[t];
            #pragma unroll
            for (int m=16;m>0;m>>=1) xx += __shfl_xor_sync(0xffffffffu, xx, m);
            if (t==0) red[33] = xx;
        }
        __syncthreads();
        float tot = red[33];
        float beta_j = sqrtf(tot);
        float invb = rsqrtf(tot + 1e-30f);
        vp[r0] = vc[r0]; vp[r1] = vc[r1];
        vc[r0] = w0*invb; vc[r1] = w1*invb;
        if (t == 0) { s_alpha[j] = alpha; s_beta[j] = beta_j; }
        beta_prev = beta_j;
        __syncthreads();
    }

    if (t < 32) {
        float lo = s_alpha[0], hi = s_alpha[0];
        float sb2[LZM];
        for (int i=0;i<LZM;i++) {
            float r = (i>0?fabsf(s_beta[i-1]):0.f) + (i<LZM-1?fabsf(s_beta[i]):0.f);
            lo = fminf(lo, s_alpha[i]-r);
            hi = fmaxf(hi, s_alpha[i]+r);
            sb2[i] = (i>0) ? s_beta[i-1]*s_beta[i-1] : 0.f;
        }
        lo -= 1.f; hi += 1.f;
        for (int round=0; round<8; round++) {
            float w  = (hi-lo)*(1.0f/33.0f);
            float xp = lo + w*(float)(t+1);
            int cnt = 0;
            float d = s_alpha[0]-xp; if (d<0.f) cnt++;
            #pragma unroll 4
            for (int i=1;i<LZM;i++){
                if (d==0.f) d = -1e-30f;
                d = s_alpha[i]-xp - __fdividef(sb2[i], d);
                if (d<0.f) cnt++;
            }
            unsigned m = __ballot_sync(0xffffffffu, cnt >= LZM);
            if (m == 0u) {
                lo = lo + w*32.f;
            } else {
                int f = __ffs(m)-1;
                hi = lo + w*(float)(f+1);
                lo = lo + w*(float)f;
            }
        }
        if (t==0) {
            float lam = 0.5f*(lo+hi) + 1e-8f;
            g_scale2 = 2.0f/lam;
        }
    }
}
#define LZ_SMEM ((2048+2048+128)*4 + CAP_E*4)

// ===== x1 epilogue: x1 = relu(LN(s2*Gy - Gx + bc)) + x  (warp per row) ======
__device__ __forceinline__ void ln_row_w(float v[8], const float* __restrict__ g,
                                         const float* __restrict__ be, int tx, bool do_relu) {
    float s = 0.f;
    #pragma unroll
    for (int u=0;u<8;u++) s += v[u];
    #pragma unroll
    for (int m=1;m<32;m<<=1) s += __shfl_xor_sync(0xffffffffu, s, m);
    float mu = s * (1.0f/256.0f);
    float q = 0.f;
    #pragma unroll
    for (int u=0;u<8;u++){ float d = v[u]-mu; q += d*d; }
    #pragma unroll
    for (int m=1;m<32;m<<=1) q += __shfl_xor_sync(0xffffffffu, q, m);
    float inv = rsqrtf(q*(1.0f/256.0f) + 1e-5f);
    #pragma unroll
    for (int u=0;u<8;u++){
        int col = (u<4) ? (tx*4+u) : (128 + tx*4 + (u-4));
        float t = (v[u]-mu)*inv*g[col] + be[col];
        if (do_relu) t = fmaxf(t, 0.f);
        v[u] = t;
    }
}

__global__ void __launch_bounds__(256) k_x1_post(const float* __restrict__ x,
                                                 const float* __restrict__ bc,
                                                 const float* __restrict__ g1,
                                                 const float* __restrict__ be1) {
    int row = blockIdx.x*8 + (threadIdx.x >> 5);
    int lane = threadIdx.x & 31;
    float s2 = g_scale2;
    const float* gy = g_gy + (size_t)row*Dd;
    const float* gx = g_gx + (size_t)row*Dd;
    float4 y0 = *(const float4*)(gy + lane*4);
    float4 y1 = *(const float4*)(gy + 128 + lane*4);
    float4 x0 = *(const float4*)(gx + lane*4);
    float4 x1 = *(const float4*)(gx + 128 + lane*4);
    int c0 = lane*4, c1 = 128 + lane*4;
    float v[8];
    v[0] = s2*y0.x - x0.x + bc[c0+0];
    v[1] = s2*y0.y - x0.y + bc[c0+1];
    v[2] = s2*y0.z - x0.z + bc[c0+2];
    v[3] = s2*y0.w - x0.w + bc[c0+3];
    v[4] = s2*y1.x - x1.x + bc[c1+0];
    v[5] = s2*y1.y - x1.y + bc[c1+1];
    v[6] = s2*y1.z - x1.z + bc[c1+2];
    v[7] = s2*y1.w - x1.w + bc[c1+3];
    ln_row_w(v, g1, be1, lane, true);
    const float* xr = x + (size_t)row*Dd;
    float4 xv0 = *(const float4*)(xr + lane*4);
    float4 xv1 = *(const float4*)(xr + 128 + lane*4);
    v[0]+=xv0.x; v[1]+=xv0.y; v[2]+=xv0.z; v[3]+=xv0.w;
    v[4]+=xv1.x; v[5]+=xv1.y; v[6]+=xv1.z; v[7]+=xv1.w;
    float* dst = g_x1 + (size_t)row*Dd;
    *(float4*)(dst + lane*4)       = make_float4(v[0], v[1], v[2], v[3]);
    *(float4*)(dst + 128 + lane*4) = make_float4(v[4], v[5], v[6], v[7]);
}

// ===================== sparse attention (exact) ==============================
__global__ void __launch_bounds__(256) k_attn_sp() {
    int wid = threadIdx.x >> 5, lane = threadIdx.x & 31;
    int gw = blockIdx.x*8 + wid;           // 0..16383
    int bh = gw >> 11;
    int n  = gw & 2047;
    int b = bh >> 2, h = bh & 3;

    const float* qg = g_q + ((size_t)bh*Nn + n)*HD;
    float2 q2 = *(const float2*)(qg + lane*2);

    int cnt = g_cnt[n];
    const int* nb = g_nbr + n*NCAP;

    int id[3] = {0,0,0};
    #pragma unroll
    for (int k=0;k<3;k++) { int j = lane + 32*k; if (j < cnt) id[k] = nb[j]; }

    const float* kg = g_kk + (size_t)bh*Nn*HD;
    float s[3] = {-1e30f,-1e30f,-1e30f};
    for (int j=0; j<cnt; j++) {
        int idx = __shfl_sync(0xffffffffu, id[j>>5], j&31);
        float2 k2 = *(const float2*)(kg + (size_t)idx*HD + lane*2);
        float d = q2.x*k2.x + q2.y*k2.y;
        #pragma unroll
        for (int m=16;m>0;m>>=1) d += __shfl_xor_sync(0xffffffffu, d, m);
        if (lane == (j&31) && (j>>5) == 0) s[0] = d*0.125f;
        if (lane == (j&31) && (j>>5) == 1) s[1] = d*0.125f;
        if (lane == (j&31) && (j>>5) == 2) s[2] = d*0.125f;
    }
    float mx = fmaxf(s[0], fmaxf(s[1], s[2]));
    #pragma unroll
    for (int m=16;m>0;m>>=1) mx = fmaxf(mx, __shfl_xor_sync(0xffffffffu, mx, m));
    float p[3];
    float l = 0.f;
    #pragma unroll
    for (int k=0;k<3;k++){ p[k] = __expf(s[k]-mx); l += p[k]; }
    #pragma unroll
    for (int m=16;m>0;m>>=1) l += __shfl_xor_sync(0xffffffffu, l, m);

    const float* vg = g_v + (size_t)bh*Nn*HD;
    float ox = 0.f, oy = 0.f;
    for (int j=0; j<cnt; j++) {
        float pj = __shfl_sync(0xffffffffu, p[j>>5], j&31);
        int  idx = __shfl_sync(0xffffffffu, id[j>>5], j&31);
        float2 v2 = *(const float2*)(vg + (size_t)idx*HD + lane*2);
        ox += pj*v2.x; oy += pj*v2.y;
    }
    float invl = 1.0f / l;
    float2 o2 = make_float2(ox*invl, oy*invl);
    *(float2*)(g_o + ((size_t)(b*Nn) + n)*Dd + h*HD + lane*2) = o2;
}

// ===================== 64x256 GEMM (3-stage cp.async, 1 bar/stage, FFMA2) ===
__device__ __forceinline__ void load_tiles64(const float* __restrict__ A, int lda,
                                             const float* __restrict__ B, int ldb,
                                             int k0, float* As, float* Bs, int tid) {
    {
        int r = tid >> 2, c = (tid & 3) * 4;
        cp16(As + r*LDA_S + c, A + (size_t)r*lda + k0 + c);
    }
    #pragma unroll
    for (int u=0; u<4; u++) {
        int o = tid*4 + u;
        int kk = o >> 6, c = (o & 63) * 4;
        cp16(Bs + kk*LDB_S + c, B + (size_t)(k0+kk)*ldb + c);
    }
}

__device__ __forceinline__ void mm64x256(const float* __restrict__ A, int lda,
                                         const float* __restrict__ B, int ldb,
                                         int K, float acc[8][8],
                                         float* As, float* Bs) {
    int tid = threadIdx.x;
    int tx = tid & 31, ty = tid >> 5;
    unsigned long long acc2[8][4];
    #pragma unroll
    for (int r=0;r<8;r++)
        #pragma unroll
        for (int p=0;p<4;p++) acc2[r][p] = 0ull;

    int T = K / 16;
    load_tiles64(A, lda, B, ldb, 0,  As,          Bs,          tid);
    cp_commit();
    load_tiles64(A, lda, B, ldb, 16, As + ASLOT,  Bs + BSLOT,  tid);
    cp_commit();

    for (int t = 0; t < T; t++) {
        cp_wait<1>();
        __syncthreads();
        if (t+2 < T) {
            int slot = (t+2) % 3;
            load_tiles64(A, lda, B, ldb, (t+2)*16,
                         As + slot*ASLOT, Bs + slot*BSLOT, tid);
            cp_commit();
        } else {
            cp_commit();
        }
        int cur = t % 3;
        const float* Asc = As + cur*ASLOT;
        const float* Bsc = Bs + cur*BSLOT;
        #pragma unroll
        for (int k4 = 0; k4 < 4; k4++) {
            float4 a[8];
            #pragma unroll
            for (int r=0;r<8;r++)
                a[r] = *(const float4*)(Asc + (8*ty+r)*LDA_S + k4*4);
            #pragma unroll
            for (int u=0;u<4;u++) {
                const float* brow = Bsc + (k4*4+u)*LDB_S;
                ulonglong2 b0 = *(const ulonglong2*)(brow + tx*4);
                ulonglong2 b1 = *(const ulonglong2*)(brow + 128 + tx*4);
                #pragma unroll
                for (int r=0;r<8;r++) {
                    float av = (u==0) ? a[r].x : (u==1) ? a[r].y : (u==2) ? a[r].z : a[r].w;
                    unsigned long long a2 = dup2(av);
                    fma2(acc2[r][0], a2, b0.x);
                    fma2(acc2[r][1], a2, b0.y);
                    fma2(acc2[r][2], a2, b1.x);
                    fma2(acc2[r][3], a2, b1.y);
                }
            }
        }
    }
    __syncthreads();
    #pragma unroll
    for (int r=0;r<8;r++)
        #pragma unroll
        for (int p=0;p<4;p++)
            unpack2(acc2[r][p], acc[r][2*p], acc[r][2*p+1]);
}

__device__ __forceinline__ void store_row8(float* dst, const float v[8], int tx) {
    *(float4*)(dst + tx*4)       = make_float4(v[0], v[1], v[2], v[3]);
    *(float4*)(dst + 128 + tx*4) = make_float4(v[4], v[5], v[6], v[7]);
}

#define GEMM_SMEM_DECL __shared__ float As[3*64*LDA_S]; __shared__ float Bs[3*16*LDB_S]

// ---- qkv = x1 @ W, stored (b,h,n,d); 2 CTA/SM (grid 384 >= 2 waves) --------
__global__ void __launch_bounds__(256, 2) k_gemm_qkv(const float* __restrict__ Wq,
                                                     const float* __restrict__ Wk,
                                                     const float* __restrict__ Wv) {
    GEMM_SMEM_DECL;
    float acc[8][8];
    const float* W = (blockIdx.y==0) ? Wq : (blockIdx.y==1) ? Wk : Wv;
    float* dst0 = (blockIdx.y==0) ? g_q : (blockIdx.y==1) ? g_kk : g_v;
    const float* A = g_x1 + (size_t)blockIdx.x*64*Dd;
    mm64x256(A, Dd, W, Dd, Dd, acc, As, Bs);
    int tx = threadIdx.x & 31, ty = threadIdx.x >> 5;
    int h0 = tx >> 4;
    int co = (tx*4) & 63;
    #pragma unroll
    for (int rr=0; rr<8; rr++) {
        int row = blockIdx.x*64 + 8*ty + rr;
        int b = row >> 11, n = row & 2047;
        *(float4*)(dst0 + ((size_t)(b*4 + h0    )*Nn + n)*HD + co) =
            make_float4(acc[rr][0], acc[rr][1], acc[rr][2], acc[rr][3]);
        *(float4*)(dst0 + ((size_t)(b*4 + 2 + h0)*Nn + n)*HD + co) =
            make_float4(acc[rr][4], acc[rr][5], acc[rr][6], acc[rr][7]);
    }
}

// ---- x2 = LN(x1 + o@Wo + bo) ------------------------------------------------
__global__ void __launch_bounds__(256) k_gemm_x2(const float* __restrict__ Wo,
                                                 const float* __restrict__ bo,
                                                 const float* __restrict__ g2,
                                                 const float* __restrict__ be2) {
    GEMM_SMEM_DECL;
    float acc[8][8];
    const float* A = g_o + (size_t)blockIdx.x*64*Dd;
    mm64x256(A, Dd, Wo, Dd, Dd, acc, As, Bs);
    int tx = threadIdx.x & 31, ty = threadIdx.x >> 5;
    #pragma unroll
    for (int rr=0; rr<8; rr++) {
        int row = blockIdx.x*64 + 8*ty + rr;
        const float* x1r = g_x1 + (size_t)row*Dd;
        float4 xv0 = *(const float4*)(x1r + tx*4);
        float4 xv1 = *(const float4*)(x1r + 128 + tx*4);
        int c0 = tx*4, c1 = 128 + tx*4;
        float v[8];
        v[0] = acc[rr][0] + bo[c0+0] + xv0.x;
        v[1] = acc[rr][1] + bo[c0+1] + xv0.y;
        v[2] = acc[rr][2] + bo[c0+2] + xv0.z;
        v[3] = acc[rr][3] + bo[c0+3] + xv0.w;
        v[4] = acc[rr][4] + bo[c1+0] + xv1.x;
        v[5] = acc[rr][5] + bo[c1+1] + xv1.y;
        v[6] = acc[rr][6] + bo[c1+2] + xv1.z;
        v[7] = acc[rr][7] + bo[c1+3] + xv1.w;
        ln_row_w(v, g2, be2, tx, false);
        store_row8(g_x2 + (size_t)row*Dd, v, tx);
    }
}

// ---- mt = gelu(x2@W1 + b1); 2 CTA/SM (grid 256) ------------------------------
__global__ void __launch_bounds__(256, 2) k_gemm_m1(const float* __restrict__ W1,
                                                    const float* __restrict__ b1) {
    GEMM_SMEM_DECL;
    float acc[8][8];
    int cb = blockIdx.y;
    const float* A = g_x2 + (size_t)blockIdx.x*64*Dd;
    mm64x256(A, Dd, W1 + cb*256, HID, Dd, acc, As, Bs);
    int tx = threadIdx.x & 31, ty = threadIdx.x >> 5;
    #pragma unroll
    for (int rr=0; rr<8; rr++) {
        int row = blockIdx.x*64 + 8*ty + rr;
        float v[8];
        #pragma unroll
        for (int u=0;u<8;u++){
            int col = (u<4) ? (tx*4+u) : (128 + tx*4 + (u-4));
            float t = acc[rr][u] + b1[cb*256 + col];
            v[u] = 0.5f*t*(1.0f + erff(t*0.70710678118654752f));
        }
        store_row8(g_mt + (size_t)row*HID + cb*256, v, tx);
    }
}

// ---- out = LN(x2 + mt@W2 + b2) ----------------------------------------------
__global__ void __launch_bounds__(256) k_gemm_out(const float* __restrict__ W2,
                                                  const float* __restrict__ b2,
                                                  const float* __restrict__ g3,
                                                  const float* __restrict__ be3,
                                                  float* __restrict__ out) {
    GEMM_SMEM_DECL;
    float acc[8][8];
    const float* A = g_mt + (size_t)blockIdx.x*64*HID;
    mm64x256(A, HID, W2, Dd, HID, acc, As, Bs);
    int tx = threadIdx.x & 31, ty = threadIdx.x >> 5;
    #pragma unroll
    for (int rr=0; rr<8; rr++) {
        int row = blockIdx.x*64 + 8*ty + rr;
        const float* x2r = g_x2 + (size_t)row*Dd;
        float4 xv0 = *(const float4*)(x2r + tx*4);
        float4 xv1 = *(const float4*)(x2r + 128 + tx*4);
        int c0 = tx*4, c1 = 128 + tx*4;
        float v[8];
        v[0] = acc[rr][0] + b2[c0+0] + xv0.x;
        v[1] = acc[rr][1] + b2[c0+1] + xv0.y;
        v[2] = acc[rr][2] + b2[c0+2] + xv0.z;
        v[3] = acc[rr][3] + b2[c0+3] + xv0.w;
        v[4] = acc[rr][4] + b2[c1+0] + xv1.x;
        v[5] = acc[rr][5] + b2[c1+1] + xv1.y;
        v[6] = acc[rr][6] + b2[c1+2] + xv1.z;
        v[7] = acc[rr][7] + b2[c1+3] + xv1.w;
        ln_row_w(v, g3, be3, tx, false);
        store_row8(out + (size_t)row*Dd, v, tx);
    }
}

// ============================ launch =========================================
extern "C" void kernel_launch(void* const* d_in, const int* in_sizes, int n_in,
                              void* d_out, int out_size) {
    const float* x   = (const float*)d_in[0];
    const float* L   = (const float*)d_in[1];
    const float* adj = (const float*)d_in[2];
    const float* Wc  = (const float*)d_in[3];
    const float* bc  = (const float*)d_in[4];
    const float* g1  = (const float*)d_in[5];
    const float* be1 = (const float*)d_in[6];
    const float* Wq  = (const float*)d_in[7];
    const float* Wk  = (const float*)d_in[8];
    const float* Wv  = (const float*)d_in[9];
    const float* Wo  = (const float*)d_in[10];
    const float* bo  = (const float*)d_in[11];
    const float* g2  = (const float*)d_in[12];
    const float* be2 = (const float*)d_in[13];
    const float* W1  = (const float*)d_in[14];
    const float* b1  = (const float*)d_in[15];
    const float* W2  = (const float*)d_in[16];
    const float* b2  = (const float*)d_in[17];
    const float* g3  = (const float*)d_in[18];
    const float* be3 = (const float*)d_in[19];
    float* out = (float*)d_out;

    cudaFuncSetAttribute(k_fat, cudaFuncAttributeMaxDynamicSharedMemorySize, LZ_SMEM);

    k_build_nbr<<<Nn, 256>>>(adj);                          // 1
    k_fat      <<<1 + Mrows/64, 1024, LZ_SMEM>>>(L, x, Wc); // 2: lz || y+Gy+Gx
    k_x1_post  <<<Mrows/8, 256>>>(x, bc, g1, be1);          // 3
    k_gemm_qkv <<<dim3(Mrows/64, 3), 256>>>(Wq, Wk, Wv);    // 4  <-- ncu
    k_attn_sp  <<<Bz*4*Nn/8, 256>>>();                      // 5
    k_gemm_x2  <<<Mrows/64, 256>>>(Wo, bo, g2, be2);        // 6
    k_gemm_m1  <<<dim3(Mrows/64, 2), 256>>>(W1, b1);        // 7
    k_gemm_out <<<Mrows/64, 256>>>(W2, b2, g3, be3, out);   // 8
}